// round 5
// baseline (speedup 1.0000x reference)
#include <cuda_runtime.h>
#include <cuda_bf16.h>
#include <cstdint>

// Problem dims
#define BB 8
#define TT 1024
#define CC 2048
#define MM (BB * TT)          // 8192
#define NELEM (BB * TT * CC)  // 16,777,216

// GEMM tiling (HMMA mma.sync path) — R3 shape
#define BM 128
#define BN 128
#define BKK 32
#define NITER (CC / BKK)      // 64
#define SROWB 80              // padded row stride in bytes (40 bf16)
#define TILEB (128 * SROWB)   // 10240 bytes per tile
#define STAGEB (4 * TILEB)    // Ah, Al, Bh, Bl
#define GSMEM (2 * STAGEB)    // 81920 bytes

// ---------------------------------------------------------------------------
// Scratch (static device globals; no allocation anywhere)
// ---------------------------------------------------------------------------
__device__ __nv_bfloat16 g_xkh[NELEM], g_xkl[NELEM];
__device__ __nv_bfloat16 g_xvh[NELEM], g_xvl[NELEM];
__device__ __nv_bfloat16 g_xrh[NELEM], g_xrl[NELEM];
__device__ __nv_bfloat16 g_wh[4ULL * CC * CC], g_wl[4ULL * CC * CC];
__device__ float g_k[NELEM], g_v[NELEM], g_r[NELEM];
__device__ __nv_bfloat16 g_sh[NELEM], g_sl[NELEM];

// ---------------------------------------------------------------------------
// Helpers
// ---------------------------------------------------------------------------
__device__ __forceinline__ uint32_t smem_u32(const void* p) {
    uint32_t a;
    asm("{ .reg .u64 t; cvta.to.shared.u64 t, %1; cvt.u32.u64 %0, t; }"
        : "=r"(a) : "l"(p));
    return a;
}
__device__ __forceinline__ void cp_async16(uint32_t saddr, const void* gaddr) {
    asm volatile("cp.async.cg.shared.global [%0], [%1], 16;"
                 :: "r"(saddr), "l"(gaddr));
}
__device__ __forceinline__ void cp_commit() { asm volatile("cp.async.commit_group;"); }
__device__ __forceinline__ void cp_wait1() { asm volatile("cp.async.wait_group 1;"); }
__device__ __forceinline__ void cp_wait0() { asm volatile("cp.async.wait_group 0;"); }

__device__ __forceinline__ void ldsm_x4(uint32_t addr, uint32_t& r0, uint32_t& r1,
                                        uint32_t& r2, uint32_t& r3) {
    asm volatile("ldmatrix.sync.aligned.m8n8.x4.shared.b16 {%0,%1,%2,%3}, [%4];"
                 : "=r"(r0), "=r"(r1), "=r"(r2), "=r"(r3) : "r"(addr));
}
__device__ __forceinline__ void mma_bf16(float* c, const uint32_t* a, const uint32_t* b) {
    asm volatile(
        "mma.sync.aligned.m16n8k16.row.col.f32.bf16.bf16.f32 "
        "{%0,%1,%2,%3}, {%4,%5,%6,%7}, {%8,%9}, {%0,%1,%2,%3};"
        : "+f"(c[0]), "+f"(c[1]), "+f"(c[2]), "+f"(c[3])
        : "r"(a[0]), "r"(a[1]), "r"(a[2]), "r"(a[3]), "r"(b[0]), "r"(b[1]));
}

// fp32 -> (hi, lo) bf16 split
__device__ __forceinline__ void store_split4(__nv_bfloat16* __restrict__ hb,
                                             __nv_bfloat16* __restrict__ lb,
                                             size_t base, float4 v) {
    __nv_bfloat16 h0 = __float2bfloat16(v.x), h1 = __float2bfloat16(v.y);
    __nv_bfloat16 h2 = __float2bfloat16(v.z), h3 = __float2bfloat16(v.w);
    __nv_bfloat16 l0 = __float2bfloat16(v.x - __bfloat162float(h0));
    __nv_bfloat16 l1 = __float2bfloat16(v.y - __bfloat162float(h1));
    __nv_bfloat16 l2 = __float2bfloat16(v.z - __bfloat162float(h2));
    __nv_bfloat16 l3 = __float2bfloat16(v.w - __bfloat162float(h3));
    __nv_bfloat162 H0; H0.x = h0; H0.y = h1;
    __nv_bfloat162 H1; H1.x = h2; H1.y = h3;
    __nv_bfloat162 L0; L0.x = l0; L0.y = l1;
    __nv_bfloat162 L1; L1.x = l2; L1.y = l3;
    *reinterpret_cast<__nv_bfloat162*>(hb + base)     = H0;
    *reinterpret_cast<__nv_bfloat162*>(hb + base + 2) = H1;
    *reinterpret_cast<__nv_bfloat162*>(lb + base)     = L0;
    *reinterpret_cast<__nv_bfloat162*>(lb + base + 2) = L1;
}

// ---------------------------------------------------------------------------
// Kernel: fp32 -> split bf16 (weights)
// ---------------------------------------------------------------------------
__global__ void split_kernel(const float4* __restrict__ src,
                             __nv_bfloat16* __restrict__ dh,
                             __nv_bfloat16* __restrict__ dl, int n4) {
    int i = blockIdx.x * blockDim.x + threadIdx.x;
    if (i >= n4) return;
    store_split4(dh, dl, (size_t)i * 4, src[i]);
}

// ---------------------------------------------------------------------------
// Kernel: time-shift mixing fused with bf16 split
// ---------------------------------------------------------------------------
__global__ void mix_split_kernel(const float4* __restrict__ x4,
                                 const float4* __restrict__ tmk4,
                                 const float4* __restrict__ tmv4,
                                 const float4* __restrict__ tmr4) {
    const int C4 = CC / 4;
    int i = blockIdx.x * blockDim.x + threadIdx.x;
    if (i >= NELEM / 4) return;
    int c4 = i % C4;
    int t = (i / C4) % TT;

    float4 xc = x4[i];
    float4 xs = make_float4(0.f, 0.f, 0.f, 0.f);
    if (t > 0) xs = x4[i - C4];

    float4 mk = tmk4[c4], mv = tmv4[c4], mr = tmr4[c4];
    float4 ok, ov, orr;
    ok.x  = xc.x * mk.x + xs.x * (1.f - mk.x);
    ok.y  = xc.y * mk.y + xs.y * (1.f - mk.y);
    ok.z  = xc.z * mk.z + xs.z * (1.f - mk.z);
    ok.w  = xc.w * mk.w + xs.w * (1.f - mk.w);
    ov.x  = xc.x * mv.x + xs.x * (1.f - mv.x);
    ov.y  = xc.y * mv.y + xs.y * (1.f - mv.y);
    ov.z  = xc.z * mv.z + xs.z * (1.f - mv.z);
    ov.w  = xc.w * mv.w + xs.w * (1.f - mv.w);
    orr.x = xc.x * mr.x + xs.x * (1.f - mr.x);
    orr.y = xc.y * mr.y + xs.y * (1.f - mr.y);
    orr.z = xc.z * mr.z + xs.z * (1.f - mr.z);
    orr.w = xc.w * mr.w + xs.w * (1.f - mr.w);

    size_t base = (size_t)i * 4;
    store_split4(g_xkh, g_xkl, base, ok);
    store_split4(g_xvh, g_xvl, base, ov);
    store_split4(g_xrh, g_xrl, base, orr);
}

// ---------------------------------------------------------------------------
// Kernel: split-bf16 HMMA GEMM. C = (Ah+Al).(Bh+Bl)^T ~= AhBh+AlBh+AhBl.
// 128x128 CTA, 64x32 warp tile, BK=32, double-buffered cp.async.
// __launch_bounds__(256,2): cap regs at 128 so 2 CTAs/SM co-reside.
// Inner tile in 3 passes to keep peak fragment liveness under the cap.
// ---------------------------------------------------------------------------
__global__ __launch_bounds__(256, 2)
void gemm_hmma(const __nv_bfloat16* __restrict__ Ah,
               const __nv_bfloat16* __restrict__ Al,
               const __nv_bfloat16* __restrict__ Bh,
               const __nv_bfloat16* __restrict__ Bl,
               float* __restrict__ C) {
    extern __shared__ __align__(128) char smem[];
    const uint32_t sb = smem_u32(smem);
    const int tid = threadIdx.x;
    const int wid = tid >> 5;
    const int lane = tid & 31;
    const int wm = wid >> 2;          // 0..1
    const int wn = wid & 3;           // 0..3
    const int rowBase = blockIdx.y * BM;
    const int colBase = blockIdx.x * BN;
    const int warpRow = wm * 64;
    const int warpCol = wn * 32;

    const uint32_t OF_AH = 0, OF_AL = TILEB, OF_BH = 2 * TILEB, OF_BL = 3 * TILEB;

    auto issue_stage = [&](int buf, int k0) {
        uint32_t sbase = sb + buf * STAGEB;
#pragma unroll
        for (int it = 0; it < 2; it++) {
            int idx = tid + it * 256;
            int r = idx >> 2, c = idx & 3;
            uint32_t so = (uint32_t)(r * SROWB + c * 16);
            size_t gA = (size_t)(rowBase + r) * CC + k0 + c * 8;
            size_t gB = (size_t)(colBase + r) * CC + k0 + c * 8;
            cp_async16(sbase + OF_AH + so, Ah + gA);
            cp_async16(sbase + OF_AL + so, Al + gA);
            cp_async16(sbase + OF_BH + so, Bh + gB);
            cp_async16(sbase + OF_BL + so, Bl + gB);
        }
        cp_commit();
    };

    float acc[4][4][4];
#pragma unroll
    for (int i = 0; i < 4; i++)
#pragma unroll
        for (int j = 0; j < 4; j++)
#pragma unroll
            for (int q = 0; q < 4; q++) acc[i][j][q] = 0.f;

    // ldmatrix per-lane base offsets
    const uint32_t aLaneOff =
        (uint32_t)((warpRow + (lane & 15)) * SROWB + (lane >> 4) * 16);
    const int bg = lane >> 3, bw = lane & 7;
    const uint32_t bLaneOff =
        (uint32_t)((warpCol + (bg >> 1) * 8 + bw) * SROWB + (bg & 1) * 16);

    issue_stage(0, 0);

#pragma unroll 1
    for (int j = 0; j < NITER; j++) {
        const int buf = j & 1;
        if (j + 1 < NITER) {
            issue_stage(buf ^ 1, (j + 1) * BKK);
            cp_wait1();
        } else {
            cp_wait0();
        }
        __syncthreads();

        const uint32_t sbase = sb + buf * STAGEB;
#pragma unroll
        for (int kk = 0; kk < 2; kk++) {
            const uint32_t kOff = kk * 32;

            // Pass 1: Ah x Bh
            uint32_t ah[4][4], bx[4][2];
#pragma unroll
            for (int i = 0; i < 4; i++) {
                uint32_t ad = sbase + OF_AH + aLaneOff + i * 16 * SROWB + kOff;
                ldsm_x4(ad, ah[i][0], ah[i][1], ah[i][2], ah[i][3]);
            }
#pragma unroll
            for (int jp = 0; jp < 2; jp++) {
                uint32_t bd = sbase + OF_BH + bLaneOff + jp * 16 * SROWB + kOff;
                ldsm_x4(bd, bx[jp * 2][0], bx[jp * 2][1],
                        bx[jp * 2 + 1][0], bx[jp * 2 + 1][1]);
            }
#pragma unroll
            for (int i = 0; i < 4; i++)
#pragma unroll
                for (int jj = 0; jj < 4; jj++) mma_bf16(acc[i][jj], ah[i], bx[jj]);

            // Pass 2: Al x Bh (bx still holds Bh)
            {
                uint32_t al[4][4];
#pragma unroll
                for (int i = 0; i < 4; i++) {
                    uint32_t ad = sbase + OF_AL + aLaneOff + i * 16 * SROWB + kOff;
                    ldsm_x4(ad, al[i][0], al[i][1], al[i][2], al[i][3]);
                }
#pragma unroll
                for (int i = 0; i < 4; i++)
#pragma unroll
                    for (int jj = 0; jj < 4; jj++) mma_bf16(acc[i][jj], al[i], bx[jj]);
            }

            // Pass 3: Ah x Bl (reuse bx for Bl; al dead)
#pragma unroll
            for (int jp = 0; jp < 2; jp++) {
                uint32_t bd = sbase + OF_BL + bLaneOff + jp * 16 * SROWB + kOff;
                ldsm_x4(bd, bx[jp * 2][0], bx[jp * 2][1],
                        bx[jp * 2 + 1][0], bx[jp * 2 + 1][1]);
            }
#pragma unroll
            for (int i = 0; i < 4; i++)
#pragma unroll
                for (int jj = 0; jj < 4; jj++) mma_bf16(acc[i][jj], ah[i], bx[jj]);
        }
        __syncthreads();
    }

    // Epilogue
    const int er = lane >> 2, ec = (lane & 3) * 2;
#pragma unroll
    for (int i = 0; i < 4; i++) {
#pragma unroll
        for (int jj = 0; jj < 4; jj++) {
            size_t row0 = (size_t)(rowBase + warpRow + i * 16 + er);
            size_t col = (size_t)(colBase + warpCol + jj * 8 + ec);
            float2 v0 = make_float2(acc[i][jj][0], acc[i][jj][1]);
            float2 v1 = make_float2(acc[i][jj][2], acc[i][jj][3]);
            *reinterpret_cast<float2*>(C + row0 * CC + col) = v0;
            *reinterpret_cast<float2*>(C + (row0 + 8) * CC + col) = v1;
        }
    }
}

// ---------------------------------------------------------------------------
// Kernel: WKV recurrence + sigmoid(r) fusion; outputs split bf16
// ---------------------------------------------------------------------------
__global__ void wkv_kernel(const float* __restrict__ k,
                           const float* __restrict__ v,
                           const float* __restrict__ r,
                           const float* __restrict__ time_decay,
                           const float* __restrict__ time_first,
                           __nv_bfloat16* __restrict__ sh,
                           __nv_bfloat16* __restrict__ sl) {
    int tidg = blockIdx.x * blockDim.x + threadIdx.x;  // 0 .. B*C-1
    if (tidg >= BB * CC) return;
    int b = tidg / CC;
    int c = tidg % CC;

    const float w = -__expf(time_decay[c]);
    const float u = time_first[c];

    float num = 0.f, den = 0.f, mx = -1e38f;
    size_t base = (size_t)b * TT * CC + c;

#pragma unroll 4
    for (int t = 0; t < TT; t++) {
        size_t idx = base + (size_t)t * CC;
        float kt = k[idx];
        float vt = v[idx];
        float rv = r[idx];

        float ku = kt + u;
        float max_out = fmaxf(mx, ku);
        float e1 = __expf(mx - max_out);
        float e2 = __expf(ku - max_out);
        float o = __fdividef(e1 * num + e2 * vt, e1 * den + e2);

        float mw = mx + w;
        float max_st = fmaxf(mw, kt);
        float e1s = __expf(mw - max_st);
        float e2s = __expf(kt - max_st);
        num = e1s * num + e2s * vt;
        den = e1s * den + e2s;
        mx = max_st;

        float sr = __fdividef(1.f, 1.f + __expf(-rv));
        float val = sr * o;
        __nv_bfloat16 h = __float2bfloat16(val);
        sh[idx] = h;
        sl[idx] = __float2bfloat16(val - __bfloat162float(h));
    }
}

// ---------------------------------------------------------------------------
// Launch
// ---------------------------------------------------------------------------
extern "C" void kernel_launch(void* const* d_in, const int* in_sizes, int n_in,
                              void* d_out, int out_size) {
    const float* x   = (const float*)d_in[0];
    const float* td  = (const float*)d_in[1];
    const float* tf  = (const float*)d_in[2];
    const float* tmk = (const float*)d_in[3];
    const float* tmv = (const float*)d_in[4];
    const float* tmr = (const float*)d_in[5];
    const float* Wk  = (const float*)d_in[6];
    const float* Wv  = (const float*)d_in[7];
    const float* Wr  = (const float*)d_in[8];
    const float* Wo  = (const float*)d_in[9];
    float* out = (float*)d_out;

    static bool inited = false;
    static __nv_bfloat16 *p_xkh, *p_xkl, *p_xvh, *p_xvl, *p_xrh, *p_xrl;
    static __nv_bfloat16 *p_wh, *p_wl, *p_sh, *p_sl;
    static float *p_k, *p_v, *p_r;
    if (!inited) {
        cudaGetSymbolAddress((void**)&p_xkh, g_xkh);
        cudaGetSymbolAddress((void**)&p_xkl, g_xkl);
        cudaGetSymbolAddress((void**)&p_xvh, g_xvh);
        cudaGetSymbolAddress((void**)&p_xvl, g_xvl);
        cudaGetSymbolAddress((void**)&p_xrh, g_xrh);
        cudaGetSymbolAddress((void**)&p_xrl, g_xrl);
        cudaGetSymbolAddress((void**)&p_wh,  g_wh);
        cudaGetSymbolAddress((void**)&p_wl,  g_wl);
        cudaGetSymbolAddress((void**)&p_k,   g_k);
        cudaGetSymbolAddress((void**)&p_v,   g_v);
        cudaGetSymbolAddress((void**)&p_r,   g_r);
        cudaGetSymbolAddress((void**)&p_sh,  g_sh);
        cudaGetSymbolAddress((void**)&p_sl,  g_sl);
        cudaFuncSetAttribute(gemm_hmma,
                             cudaFuncAttributeMaxDynamicSharedMemorySize, GSMEM);
        inited = true;
    }

    // 1. split the 4 weight matrices to bf16 hi/lo
    {
        int n4 = CC * CC / 4;
        int blocks = (n4 + 255) / 256;
        split_kernel<<<blocks, 256>>>((const float4*)Wk, p_wh + 0ULL * CC * CC,
                                      p_wl + 0ULL * CC * CC, n4);
        split_kernel<<<blocks, 256>>>((const float4*)Wv, p_wh + 1ULL * CC * CC,
                                      p_wl + 1ULL * CC * CC, n4);
        split_kernel<<<blocks, 256>>>((const float4*)Wr, p_wh + 2ULL * CC * CC,
                                      p_wl + 2ULL * CC * CC, n4);
        split_kernel<<<blocks, 256>>>((const float4*)Wo, p_wh + 3ULL * CC * CC,
                                      p_wl + 3ULL * CC * CC, n4);
    }

    // 2. time-shift mixing + split
    {
        int n4 = NELEM / 4;
        mix_split_kernel<<<(n4 + 255) / 256, 256>>>(
            (const float4*)x, (const float4*)tmk, (const float4*)tmv, (const float4*)tmr);
    }

    // 3. projection GEMMs (HMMA)
    dim3 gg(CC / BN, MM / BM);  // (16, 64)
    gemm_hmma<<<gg, 256, GSMEM>>>(p_xkh, p_xkl, p_wh + 0ULL * CC * CC,
                                  p_wl + 0ULL * CC * CC, p_k);
    gemm_hmma<<<gg, 256, GSMEM>>>(p_xvh, p_xvl, p_wh + 1ULL * CC * CC,
                                  p_wl + 1ULL * CC * CC, p_v);
    gemm_hmma<<<gg, 256, GSMEM>>>(p_xrh, p_xrl, p_wh + 2ULL * CC * CC,
                                  p_wl + 2ULL * CC * CC, p_r);

    // 4. WKV recurrence + sigmoid fusion (outputs split bf16)
    {
        int threads = 128;
        int blocks = (BB * CC + threads - 1) / threads;
        wkv_kernel<<<blocks, threads>>>(p_k, p_v, p_r, td, tf, p_sh, p_sl);
    }

    // 5. output GEMM into d_out
    gemm_hmma<<<gg, 256, GSMEM>>>(p_sh, p_sl, p_wh + 3ULL * CC * CC,
                                  p_wl + 3ULL * CC * CC, out);
}

// round 6
// speedup vs baseline: 2.8931x; 2.8931x over previous
#include <cuda_runtime.h>
#include <cuda_fp16.h>
#include <cstdint>

// Problem dims
#define BB 8
#define TT 1024
#define CC 2048
#define MM (BB * TT)          // 8192
#define NELEM (BB * TT * CC)  // 16,777,216

// GEMM tiling (HMMA mma.sync, fp16 single-product)
#define BM 128
#define BN 128
#define BKK 32
#define NITER (CC / BKK)      // 64
#define SROWB 80              // padded row stride bytes (32 fp16 = 64B + 16 pad)
#define TILEB (128 * SROWB)   // 10240 bytes per tile
#define STAGEB (2 * TILEB)    // A, B
#define GSMEM (2 * STAGEB)    // 40960 bytes

// ---------------------------------------------------------------------------
// Scratch (static device globals; no allocation anywhere)
// ---------------------------------------------------------------------------
__device__ __half g_xk16[NELEM], g_xv16[NELEM], g_xr16[NELEM];
__device__ __half g_w16[4ULL * CC * CC];
__device__ float g_k[NELEM], g_v[NELEM], g_r[NELEM];
__device__ __half g_s16[NELEM];

// ---------------------------------------------------------------------------
// Helpers
// ---------------------------------------------------------------------------
__device__ __forceinline__ uint32_t smem_u32(const void* p) {
    uint32_t a;
    asm("{ .reg .u64 t; cvta.to.shared.u64 t, %1; cvt.u32.u64 %0, t; }"
        : "=r"(a) : "l"(p));
    return a;
}
__device__ __forceinline__ void cp_async16(uint32_t saddr, const void* gaddr) {
    asm volatile("cp.async.cg.shared.global [%0], [%1], 16;"
                 :: "r"(saddr), "l"(gaddr));
}
__device__ __forceinline__ void cp_commit() { asm volatile("cp.async.commit_group;"); }
__device__ __forceinline__ void cp_wait1() { asm volatile("cp.async.wait_group 1;"); }
__device__ __forceinline__ void cp_wait0() { asm volatile("cp.async.wait_group 0;"); }

__device__ __forceinline__ void ldsm_x4(uint32_t addr, uint32_t& r0, uint32_t& r1,
                                        uint32_t& r2, uint32_t& r3) {
    asm volatile("ldmatrix.sync.aligned.m8n8.x4.shared.b16 {%0,%1,%2,%3}, [%4];"
                 : "=r"(r0), "=r"(r1), "=r"(r2), "=r"(r3) : "r"(addr));
}
__device__ __forceinline__ void mma_f16(float* c, const uint32_t* a, const uint32_t* b) {
    asm volatile(
        "mma.sync.aligned.m16n8k16.row.col.f32.f16.f16.f32 "
        "{%0,%1,%2,%3}, {%4,%5,%6,%7}, {%8,%9}, {%0,%1,%2,%3};"
        : "+f"(c[0]), "+f"(c[1]), "+f"(c[2]), "+f"(c[3])
        : "r"(a[0]), "r"(a[1]), "r"(a[2]), "r"(a[3]), "r"(b[0]), "r"(b[1]));
}

__device__ __forceinline__ void store_h4(__half* __restrict__ dst, size_t base, float4 v) {
    __half2 a = __floats2half2_rn(v.x, v.y);
    __half2 b = __floats2half2_rn(v.z, v.w);
    *reinterpret_cast<__half2*>(dst + base)     = a;
    *reinterpret_cast<__half2*>(dst + base + 2) = b;
}

// ---------------------------------------------------------------------------
// Kernel: fp32 -> fp16 convert (weights)
// ---------------------------------------------------------------------------
__global__ void cvt16_kernel(const float4* __restrict__ src,
                             __half* __restrict__ dst, int n4) {
    int i = blockIdx.x * blockDim.x + threadIdx.x;
    if (i >= n4) return;
    store_h4(dst, (size_t)i * 4, src[i]);
}

// ---------------------------------------------------------------------------
// Kernel: time-shift mixing fused with fp16 convert
// ---------------------------------------------------------------------------
__global__ void mix16_kernel(const float4* __restrict__ x4,
                             const float4* __restrict__ tmk4,
                             const float4* __restrict__ tmv4,
                             const float4* __restrict__ tmr4) {
    const int C4 = CC / 4;
    int i = blockIdx.x * blockDim.x + threadIdx.x;
    if (i >= NELEM / 4) return;
    int c4 = i % C4;
    int t = (i / C4) % TT;

    float4 xc = x4[i];
    float4 xs = make_float4(0.f, 0.f, 0.f, 0.f);
    if (t > 0) xs = x4[i - C4];

    float4 mk = tmk4[c4], mv = tmv4[c4], mr = tmr4[c4];
    float4 ok, ov, orr;
    ok.x  = xc.x * mk.x + xs.x * (1.f - mk.x);
    ok.y  = xc.y * mk.y + xs.y * (1.f - mk.y);
    ok.z  = xc.z * mk.z + xs.z * (1.f - mk.z);
    ok.w  = xc.w * mk.w + xs.w * (1.f - mk.w);
    ov.x  = xc.x * mv.x + xs.x * (1.f - mv.x);
    ov.y  = xc.y * mv.y + xs.y * (1.f - mv.y);
    ov.z  = xc.z * mv.z + xs.z * (1.f - mv.z);
    ov.w  = xc.w * mv.w + xs.w * (1.f - mv.w);
    orr.x = xc.x * mr.x + xs.x * (1.f - mr.x);
    orr.y = xc.y * mr.y + xs.y * (1.f - mr.y);
    orr.z = xc.z * mr.z + xs.z * (1.f - mr.z);
    orr.w = xc.w * mr.w + xs.w * (1.f - mr.w);

    size_t base = (size_t)i * 4;
    store_h4(g_xk16, base, ok);
    store_h4(g_xv16, base, ov);
    store_h4(g_xr16, base, orr);
}

// ---------------------------------------------------------------------------
// Kernel: fp16 HMMA GEMM. C[M,N] = A[M,K] . B[N,K]^T, fp32 accumulate.
// 128x128 CTA, 64x32 warp tile, BK=32, double-buffered cp.async.
// Low register pressure -> 2 CTAs/SM (40KB smem each).
// ---------------------------------------------------------------------------
__global__ __launch_bounds__(256, 2)
void gemm_f16(const __half* __restrict__ A,
              const __half* __restrict__ B,
              float* __restrict__ C) {
    extern __shared__ __align__(128) char smem[];
    const uint32_t sb = smem_u32(smem);
    const int tid = threadIdx.x;
    const int wid = tid >> 5;
    const int lane = tid & 31;
    const int wm = wid >> 2;          // 0..1
    const int wn = wid & 3;           // 0..3
    const int rowBase = blockIdx.y * BM;
    const int colBase = blockIdx.x * BN;
    const int warpRow = wm * 64;
    const int warpCol = wn * 32;

    const uint32_t OF_A = 0, OF_B = TILEB;

    auto issue_stage = [&](int buf, int k0) {
        uint32_t sbase = sb + buf * STAGEB;
#pragma unroll
        for (int it = 0; it < 2; it++) {
            int idx = tid + it * 256;
            int r = idx >> 2, c = idx & 3;
            uint32_t so = (uint32_t)(r * SROWB + c * 16);
            size_t gA = (size_t)(rowBase + r) * CC + k0 + c * 8;
            size_t gB = (size_t)(colBase + r) * CC + k0 + c * 8;
            cp_async16(sbase + OF_A + so, A + gA);
            cp_async16(sbase + OF_B + so, B + gB);
        }
        cp_commit();
    };

    float acc[4][4][4];
#pragma unroll
    for (int i = 0; i < 4; i++)
#pragma unroll
        for (int j = 0; j < 4; j++)
#pragma unroll
            for (int q = 0; q < 4; q++) acc[i][j][q] = 0.f;

    // ldmatrix per-lane base offsets
    const uint32_t aLaneOff =
        (uint32_t)((warpRow + (lane & 15)) * SROWB + (lane >> 4) * 16);
    const int bg = lane >> 3, bw = lane & 7;
    const uint32_t bLaneOff =
        (uint32_t)((warpCol + (bg >> 1) * 8 + bw) * SROWB + (bg & 1) * 16);

    issue_stage(0, 0);

#pragma unroll 1
    for (int j = 0; j < NITER; j++) {
        const int buf = j & 1;
        if (j + 1 < NITER) {
            issue_stage(buf ^ 1, (j + 1) * BKK);
            cp_wait1();
        } else {
            cp_wait0();
        }
        __syncthreads();

        const uint32_t sbase = sb + buf * STAGEB;
#pragma unroll
        for (int kk = 0; kk < 2; kk++) {
            const uint32_t kOff = kk * 32;
            uint32_t ah[4][4], bx[4][2];
#pragma unroll
            for (int i = 0; i < 4; i++) {
                uint32_t ad = sbase + OF_A + aLaneOff + i * 16 * SROWB + kOff;
                ldsm_x4(ad, ah[i][0], ah[i][1], ah[i][2], ah[i][3]);
            }
#pragma unroll
            for (int jp = 0; jp < 2; jp++) {
                uint32_t bd = sbase + OF_B + bLaneOff + jp * 16 * SROWB + kOff;
                ldsm_x4(bd, bx[jp * 2][0], bx[jp * 2][1],
                        bx[jp * 2 + 1][0], bx[jp * 2 + 1][1]);
            }
#pragma unroll
            for (int i = 0; i < 4; i++)
#pragma unroll
                for (int jj = 0; jj < 4; jj++) mma_f16(acc[i][jj], ah[i], bx[jj]);
        }
        __syncthreads();
    }

    // Epilogue
    const int er = lane >> 2, ec = (lane & 3) * 2;
#pragma unroll
    for (int i = 0; i < 4; i++) {
#pragma unroll
        for (int jj = 0; jj < 4; jj++) {
            size_t row0 = (size_t)(rowBase + warpRow + i * 16 + er);
            size_t col = (size_t)(colBase + warpCol + jj * 8 + ec);
            float2 v0 = make_float2(acc[i][jj][0], acc[i][jj][1]);
            float2 v1 = make_float2(acc[i][jj][2], acc[i][jj][3]);
            *reinterpret_cast<float2*>(C + row0 * CC + col) = v0;
            *reinterpret_cast<float2*>(C + (row0 + 8) * CC + col) = v1;
        }
    }
}

// ---------------------------------------------------------------------------
// Kernel: WKV recurrence + sigmoid(r) fusion; outputs fp16
// ---------------------------------------------------------------------------
__global__ void wkv_kernel(const float* __restrict__ k,
                           const float* __restrict__ v,
                           const float* __restrict__ r,
                           const float* __restrict__ time_decay,
                           const float* __restrict__ time_first,
                           __half* __restrict__ s) {
    int tidg = blockIdx.x * blockDim.x + threadIdx.x;  // 0 .. B*C-1
    if (tidg >= BB * CC) return;
    int b = tidg / CC;
    int c = tidg % CC;

    const float w = -__expf(time_decay[c]);
    const float u = time_first[c];

    float num = 0.f, den = 0.f, mx = -1e38f;
    size_t base = (size_t)b * TT * CC + c;

#pragma unroll 4
    for (int t = 0; t < TT; t++) {
        size_t idx = base + (size_t)t * CC;
        float kt = k[idx];
        float vt = v[idx];
        float rv = r[idx];

        float ku = kt + u;
        float max_out = fmaxf(mx, ku);
        float e1 = __expf(mx - max_out);
        float e2 = __expf(ku - max_out);
        float o = __fdividef(e1 * num + e2 * vt, e1 * den + e2);

        float mw = mx + w;
        float max_st = fmaxf(mw, kt);
        float e1s = __expf(mw - max_st);
        float e2s = __expf(kt - max_st);
        num = e1s * num + e2s * vt;
        den = e1s * den + e2s;
        mx = max_st;

        float sr = __fdividef(1.f, 1.f + __expf(-rv));
        s[idx] = __float2half_rn(sr * o);
    }
}

// ---------------------------------------------------------------------------
// Launch
// ---------------------------------------------------------------------------
extern "C" void kernel_launch(void* const* d_in, const int* in_sizes, int n_in,
                              void* d_out, int out_size) {
    const float* x   = (const float*)d_in[0];
    const float* td  = (const float*)d_in[1];
    const float* tf  = (const float*)d_in[2];
    const float* tmk = (const float*)d_in[3];
    const float* tmv = (const float*)d_in[4];
    const float* tmr = (const float*)d_in[5];
    const float* Wk  = (const float*)d_in[6];
    const float* Wv  = (const float*)d_in[7];
    const float* Wr  = (const float*)d_in[8];
    const float* Wo  = (const float*)d_in[9];
    float* out = (float*)d_out;

    static bool inited = false;
    static __half *p_xk, *p_xv, *p_xr, *p_w, *p_s;
    static float *p_k, *p_v, *p_r;
    if (!inited) {
        cudaGetSymbolAddress((void**)&p_xk, g_xk16);
        cudaGetSymbolAddress((void**)&p_xv, g_xv16);
        cudaGetSymbolAddress((void**)&p_xr, g_xr16);
        cudaGetSymbolAddress((void**)&p_w,  g_w16);
        cudaGetSymbolAddress((void**)&p_k,  g_k);
        cudaGetSymbolAddress((void**)&p_v,  g_v);
        cudaGetSymbolAddress((void**)&p_r,  g_r);
        cudaGetSymbolAddress((void**)&p_s,  g_s16);
        cudaFuncSetAttribute(gemm_f16,
                             cudaFuncAttributeMaxDynamicSharedMemorySize, GSMEM);
        inited = true;
    }

    // 1. convert the 4 weight matrices to fp16
    {
        int n4 = CC * CC / 4;
        int blocks = (n4 + 255) / 256;
        cvt16_kernel<<<blocks, 256>>>((const float4*)Wk, p_w + 0ULL * CC * CC, n4);
        cvt16_kernel<<<blocks, 256>>>((const float4*)Wv, p_w + 1ULL * CC * CC, n4);
        cvt16_kernel<<<blocks, 256>>>((const float4*)Wr, p_w + 2ULL * CC * CC, n4);
        cvt16_kernel<<<blocks, 256>>>((const float4*)Wo, p_w + 3ULL * CC * CC, n4);
    }

    // 2. time-shift mixing + fp16 convert
    {
        int n4 = NELEM / 4;
        mix16_kernel<<<(n4 + 255) / 256, 256>>>(
            (const float4*)x, (const float4*)tmk, (const float4*)tmv, (const float4*)tmr);
    }

    // 3. projection GEMMs (fp16 HMMA)
    dim3 gg(CC / BN, MM / BM);  // (16, 64)
    gemm_f16<<<gg, 256, GSMEM>>>(p_xk, p_w + 0ULL * CC * CC, p_k);
    gemm_f16<<<gg, 256, GSMEM>>>(p_xv, p_w + 1ULL * CC * CC, p_v);
    gemm_f16<<<gg, 256, GSMEM>>>(p_xr, p_w + 2ULL * CC * CC, p_r);

    // 4. WKV recurrence + sigmoid fusion (outputs fp16)
    {
        int threads = 128;
        int blocks = (BB * CC + threads - 1) / threads;
        wkv_kernel<<<blocks, threads>>>(p_k, p_v, p_r, td, tf, p_s);
    }

    // 5. output GEMM into d_out
    gemm_f16<<<gg, 256, GSMEM>>>(p_s, p_w + 3ULL * CC * CC, out);
}

// round 7
// speedup vs baseline: 3.6079x; 1.2471x over previous
#include <cuda_runtime.h>
#include <cuda_fp16.h>
#include <cstdint>

// Problem dims
#define BB 8
#define TT 1024
#define CC 2048
#define MM (BB * TT)          // 8192
#define NELEM (BB * TT * CC)  // 16,777,216

// WKV chunking
#define NCHK 16
#define LCHK (TT / NCHK)      // 64
#define NBC (BB * CC)         // 16384

// GEMM tiling (HMMA mma.sync, fp16 single-product)
#define BM 128
#define BN 128
#define BKK 32
#define NITER (CC / BKK)      // 64
#define SROWB 80
#define TILEB (128 * SROWB)   // 10240
#define STAGEB (2 * TILEB)
#define GSMEM (2 * STAGEB)    // 40960

// ---------------------------------------------------------------------------
// Scratch (static device globals; no allocation anywhere)
// ---------------------------------------------------------------------------
__device__ __half g_xk16[NELEM], g_xv16[NELEM], g_xr16[NELEM];
__device__ __half g_w16[4ULL * CC * CC];
__device__ float g_k[NELEM], g_v[NELEM], g_r[NELEM];
__device__ __half g_s16[NELEM];
// wkv chunk-scan scratch
__device__ float g_sv[NCHK * NBC], g_sd[NCHK * NBC], g_sm[NCHK * NBC];
__device__ float g_inum[NCHK * NBC], g_iden[NCHK * NBC], g_imx[NCHK * NBC];

// ---------------------------------------------------------------------------
// Helpers
// ---------------------------------------------------------------------------
__device__ __forceinline__ uint32_t smem_u32(const void* p) {
    uint32_t a;
    asm("{ .reg .u64 t; cvta.to.shared.u64 t, %1; cvt.u32.u64 %0, t; }"
        : "=r"(a) : "l"(p));
    return a;
}
__device__ __forceinline__ void cp_async16(uint32_t saddr, const void* gaddr) {
    asm volatile("cp.async.cg.shared.global [%0], [%1], 16;"
                 :: "r"(saddr), "l"(gaddr));
}
__device__ __forceinline__ void cp_commit() { asm volatile("cp.async.commit_group;"); }
__device__ __forceinline__ void cp_wait1() { asm volatile("cp.async.wait_group 1;"); }
__device__ __forceinline__ void cp_wait0() { asm volatile("cp.async.wait_group 0;"); }

__device__ __forceinline__ void ldsm_x4(uint32_t addr, uint32_t& r0, uint32_t& r1,
                                        uint32_t& r2, uint32_t& r3) {
    asm volatile("ldmatrix.sync.aligned.m8n8.x4.shared.b16 {%0,%1,%2,%3}, [%4];"
                 : "=r"(r0), "=r"(r1), "=r"(r2), "=r"(r3) : "r"(addr));
}
__device__ __forceinline__ void mma_f16(float* c, const uint32_t* a, const uint32_t* b) {
    asm volatile(
        "mma.sync.aligned.m16n8k16.row.col.f32.f16.f16.f32 "
        "{%0,%1,%2,%3}, {%4,%5,%6,%7}, {%8,%9}, {%0,%1,%2,%3};"
        : "+f"(c[0]), "+f"(c[1]), "+f"(c[2]), "+f"(c[3])
        : "r"(a[0]), "r"(a[1]), "r"(a[2]), "r"(a[3]), "r"(b[0]), "r"(b[1]));
}

__device__ __forceinline__ void store_h4(__half* __restrict__ dst, size_t base, float4 v) {
    __half2 a = __floats2half2_rn(v.x, v.y);
    __half2 b = __floats2half2_rn(v.z, v.w);
    *reinterpret_cast<__half2*>(dst + base)     = a;
    *reinterpret_cast<__half2*>(dst + base + 2) = b;
}

// ---------------------------------------------------------------------------
// Kernel: fp32 -> fp16 convert (weights)
// ---------------------------------------------------------------------------
__global__ void cvt16_kernel(const float4* __restrict__ src,
                             __half* __restrict__ dst, int n4) {
    int i = blockIdx.x * blockDim.x + threadIdx.x;
    if (i >= n4) return;
    store_h4(dst, (size_t)i * 4, src[i]);
}

// ---------------------------------------------------------------------------
// Kernel: time-shift mixing fused with fp16 convert
// ---------------------------------------------------------------------------
__global__ void mix16_kernel(const float4* __restrict__ x4,
                             const float4* __restrict__ tmk4,
                             const float4* __restrict__ tmv4,
                             const float4* __restrict__ tmr4) {
    const int C4 = CC / 4;
    int i = blockIdx.x * blockDim.x + threadIdx.x;
    if (i >= NELEM / 4) return;
    int c4 = i % C4;
    int t = (i / C4) % TT;

    float4 xc = x4[i];
    float4 xs = make_float4(0.f, 0.f, 0.f, 0.f);
    if (t > 0) xs = x4[i - C4];

    float4 mk = tmk4[c4], mv = tmv4[c4], mr = tmr4[c4];
    float4 ok, ov, orr;
    ok.x  = xc.x * mk.x + xs.x * (1.f - mk.x);
    ok.y  = xc.y * mk.y + xs.y * (1.f - mk.y);
    ok.z  = xc.z * mk.z + xs.z * (1.f - mk.z);
    ok.w  = xc.w * mk.w + xs.w * (1.f - mk.w);
    ov.x  = xc.x * mv.x + xs.x * (1.f - mv.x);
    ov.y  = xc.y * mv.y + xs.y * (1.f - mv.y);
    ov.z  = xc.z * mv.z + xs.z * (1.f - mv.z);
    ov.w  = xc.w * mv.w + xs.w * (1.f - mv.w);
    orr.x = xc.x * mr.x + xs.x * (1.f - mr.x);
    orr.y = xc.y * mr.y + xs.y * (1.f - mr.y);
    orr.z = xc.z * mr.z + xs.z * (1.f - mr.z);
    orr.w = xc.w * mr.w + xs.w * (1.f - mr.w);

    size_t base = (size_t)i * 4;
    store_h4(g_xk16, base, ok);
    store_h4(g_xv16, base, ov);
    store_h4(g_xr16, base, orr);
}

// ---------------------------------------------------------------------------
// Kernel: fp16 HMMA GEMM (R6 shape — unchanged)
// ---------------------------------------------------------------------------
__global__ __launch_bounds__(256, 2)
void gemm_f16(const __half* __restrict__ A,
              const __half* __restrict__ B,
              float* __restrict__ C) {
    extern __shared__ __align__(128) char smem[];
    const uint32_t sb = smem_u32(smem);
    const int tid = threadIdx.x;
    const int wid = tid >> 5;
    const int lane = tid & 31;
    const int wm = wid >> 2;
    const int wn = wid & 3;
    const int rowBase = blockIdx.y * BM;
    const int colBase = blockIdx.x * BN;
    const int warpRow = wm * 64;
    const int warpCol = wn * 32;

    const uint32_t OF_A = 0, OF_B = TILEB;

    auto issue_stage = [&](int buf, int k0) {
        uint32_t sbase = sb + buf * STAGEB;
#pragma unroll
        for (int it = 0; it < 2; it++) {
            int idx = tid + it * 256;
            int r = idx >> 2, c = idx & 3;
            uint32_t so = (uint32_t)(r * SROWB + c * 16);
            size_t gA = (size_t)(rowBase + r) * CC + k0 + c * 8;
            size_t gB = (size_t)(colBase + r) * CC + k0 + c * 8;
            cp_async16(sbase + OF_A + so, A + gA);
            cp_async16(sbase + OF_B + so, B + gB);
        }
        cp_commit();
    };

    float acc[4][4][4];
#pragma unroll
    for (int i = 0; i < 4; i++)
#pragma unroll
        for (int j = 0; j < 4; j++)
#pragma unroll
            for (int q = 0; q < 4; q++) acc[i][j][q] = 0.f;

    const uint32_t aLaneOff =
        (uint32_t)((warpRow + (lane & 15)) * SROWB + (lane >> 4) * 16);
    const int bg = lane >> 3, bw = lane & 7;
    const uint32_t bLaneOff =
        (uint32_t)((warpCol + (bg >> 1) * 8 + bw) * SROWB + (bg & 1) * 16);

    issue_stage(0, 0);

#pragma unroll 1
    for (int j = 0; j < NITER; j++) {
        const int buf = j & 1;
        if (j + 1 < NITER) {
            issue_stage(buf ^ 1, (j + 1) * BKK);
            cp_wait1();
        } else {
            cp_wait0();
        }
        __syncthreads();

        const uint32_t sbase = sb + buf * STAGEB;
#pragma unroll
        for (int kk = 0; kk < 2; kk++) {
            const uint32_t kOff = kk * 32;
            uint32_t ah[4][4], bx[4][2];
#pragma unroll
            for (int i = 0; i < 4; i++) {
                uint32_t ad = sbase + OF_A + aLaneOff + i * 16 * SROWB + kOff;
                ldsm_x4(ad, ah[i][0], ah[i][1], ah[i][2], ah[i][3]);
            }
#pragma unroll
            for (int jp = 0; jp < 2; jp++) {
                uint32_t bd = sbase + OF_B + bLaneOff + jp * 16 * SROWB + kOff;
                ldsm_x4(bd, bx[jp * 2][0], bx[jp * 2][1],
                        bx[jp * 2 + 1][0], bx[jp * 2 + 1][1]);
            }
#pragma unroll
            for (int i = 0; i < 4; i++)
#pragma unroll
                for (int jj = 0; jj < 4; jj++) mma_f16(acc[i][jj], ah[i], bx[jj]);
        }
        __syncthreads();
    }

    const int er = lane >> 2, ec = (lane & 3) * 2;
#pragma unroll
    for (int i = 0; i < 4; i++) {
#pragma unroll
        for (int jj = 0; jj < 4; jj++) {
            size_t row0 = (size_t)(rowBase + warpRow + i * 16 + er);
            size_t col = (size_t)(colBase + warpCol + jj * 8 + ec);
            float2 v0 = make_float2(acc[i][jj][0], acc[i][jj][1]);
            float2 v1 = make_float2(acc[i][jj][2], acc[i][jj][3]);
            *reinterpret_cast<float2*>(C + row0 * CC + col) = v0;
            *reinterpret_cast<float2*>(C + (row0 + 8) * CC + col) = v1;
        }
    }
}

// ---------------------------------------------------------------------------
// WKV pass 1: per-(chunk, b, c) local stabilized sums with zero initial state
// ---------------------------------------------------------------------------
__global__ void wkv_pass1(const float* __restrict__ k,
                          const float* __restrict__ v,
                          const float* __restrict__ time_decay) {
    int idx = blockIdx.x * blockDim.x + threadIdx.x;
    if (idx >= NCHK * NBC) return;
    int c = idx % CC;
    int b = (idx / CC) % BB;
    int chunk = idx / NBC;

    const float w = -__expf(time_decay[c]);
    float s_v = 0.f, s_d = 0.f, m = -1e38f;
    size_t base = ((size_t)b * TT + chunk * LCHK) * CC + c;

#pragma unroll 4
    for (int t = 0; t < LCHK; t++) {
        size_t g = base + (size_t)t * CC;
        float kt = k[g];
        float vt = v[g];
        float mw = m + w;
        float mn = fmaxf(mw, kt);
        float e1 = __expf(mw - mn);
        float e2 = __expf(kt - mn);
        s_v = e1 * s_v + e2 * vt;
        s_d = e1 * s_d + e2;
        m = mn;
    }
    g_sv[idx] = s_v;
    g_sd[idx] = s_d;
    g_sm[idx] = m;
}

// ---------------------------------------------------------------------------
// WKV pass 2: sequential prefix over chunks per (b, c); stores incoming states
// ---------------------------------------------------------------------------
__global__ void wkv_pass2(const float* __restrict__ time_decay) {
    int idx = blockIdx.x * blockDim.x + threadIdx.x;
    if (idx >= NBC) return;
    int c = idx % CC;
    const float w = -__expf(time_decay[c]);
    const float Lw = (float)LCHK * w;

    float num = 0.f, den = 0.f, mx = -1e38f;
#pragma unroll
    for (int ch = 0; ch < NCHK; ch++) {
        size_t o = (size_t)ch * NBC + idx;
        g_inum[o] = num;
        g_iden[o] = den;
        g_imx[o] = mx;
        float ms = g_sm[o];
        float mo = mx + Lw;
        float mn = fmaxf(mo, ms);
        float e1 = __expf(mo - mn);
        float e2 = __expf(ms - mn);
        num = e1 * num + e2 * g_sv[o];
        den = e1 * den + e2 * g_sd[o];
        mx = mn;
    }
}

// ---------------------------------------------------------------------------
// WKV pass 3: replay reference step inside each chunk from incoming state;
// fuse sigmoid(r) and emit fp16
// ---------------------------------------------------------------------------
__global__ void wkv_pass3(const float* __restrict__ k,
                          const float* __restrict__ v,
                          const float* __restrict__ r,
                          const float* __restrict__ time_decay,
                          const float* __restrict__ time_first,
                          __half* __restrict__ s) {
    int idx = blockIdx.x * blockDim.x + threadIdx.x;
    if (idx >= NCHK * NBC) return;
    int c = idx % CC;
    int b = (idx / CC) % BB;
    int chunk = idx / NBC;

    const float w = -__expf(time_decay[c]);
    const float u = time_first[c];

    float num = g_inum[idx];
    float den = g_iden[idx];
    float mx  = g_imx[idx];
    size_t base = ((size_t)b * TT + chunk * LCHK) * CC + c;

#pragma unroll 2
    for (int t = 0; t < LCHK; t++) {
        size_t g = base + (size_t)t * CC;
        float kt = k[g];
        float vt = v[g];
        float rv = r[g];

        float ku = kt + u;
        float max_out = fmaxf(mx, ku);
        float e1 = __expf(mx - max_out);
        float e2 = __expf(ku - max_out);
        float o = __fdividef(e1 * num + e2 * vt, e1 * den + e2);

        float mw = mx + w;
        float max_st = fmaxf(mw, kt);
        float e1s = __expf(mw - max_st);
        float e2s = __expf(kt - max_st);
        num = e1s * num + e2s * vt;
        den = e1s * den + e2s;
        mx = max_st;

        float sr = __fdividef(1.f, 1.f + __expf(-rv));
        s[g] = __float2half_rn(sr * o);
    }
}

// ---------------------------------------------------------------------------
// Launch
// ---------------------------------------------------------------------------
extern "C" void kernel_launch(void* const* d_in, const int* in_sizes, int n_in,
                              void* d_out, int out_size) {
    const float* x   = (const float*)d_in[0];
    const float* td  = (const float*)d_in[1];
    const float* tf  = (const float*)d_in[2];
    const float* tmk = (const float*)d_in[3];
    const float* tmv = (const float*)d_in[4];
    const float* tmr = (const float*)d_in[5];
    const float* Wk  = (const float*)d_in[6];
    const float* Wv  = (const float*)d_in[7];
    const float* Wr  = (const float*)d_in[8];
    const float* Wo  = (const float*)d_in[9];
    float* out = (float*)d_out;

    static bool inited = false;
    static __half *p_xk, *p_xv, *p_xr, *p_w, *p_s;
    static float *p_k, *p_v, *p_r;
    if (!inited) {
        cudaGetSymbolAddress((void**)&p_xk, g_xk16);
        cudaGetSymbolAddress((void**)&p_xv, g_xv16);
        cudaGetSymbolAddress((void**)&p_xr, g_xr16);
        cudaGetSymbolAddress((void**)&p_w,  g_w16);
        cudaGetSymbolAddress((void**)&p_k,  g_k);
        cudaGetSymbolAddress((void**)&p_v,  g_v);
        cudaGetSymbolAddress((void**)&p_r,  g_r);
        cudaGetSymbolAddress((void**)&p_s,  g_s16);
        cudaFuncSetAttribute(gemm_f16,
                             cudaFuncAttributeMaxDynamicSharedMemorySize, GSMEM);
        inited = true;
    }

    // 1. convert the 4 weight matrices to fp16
    {
        int n4 = CC * CC / 4;
        int blocks = (n4 + 255) / 256;
        cvt16_kernel<<<blocks, 256>>>((const float4*)Wk, p_w + 0ULL * CC * CC, n4);
        cvt16_kernel<<<blocks, 256>>>((const float4*)Wv, p_w + 1ULL * CC * CC, n4);
        cvt16_kernel<<<blocks, 256>>>((const float4*)Wr, p_w + 2ULL * CC * CC, n4);
        cvt16_kernel<<<blocks, 256>>>((const float4*)Wo, p_w + 3ULL * CC * CC, n4);
    }

    // 2. time-shift mixing + fp16 convert
    {
        int n4 = NELEM / 4;
        mix16_kernel<<<(n4 + 255) / 256, 256>>>(
            (const float4*)x, (const float4*)tmk, (const float4*)tmv, (const float4*)tmr);
    }

    // 3. projection GEMMs (fp16 HMMA)
    dim3 gg(CC / BN, MM / BM);  // (16, 64)
    gemm_f16<<<gg, 256, GSMEM>>>(p_xk, p_w + 0ULL * CC * CC, p_k);
    gemm_f16<<<gg, 256, GSMEM>>>(p_xv, p_w + 1ULL * CC * CC, p_v);
    gemm_f16<<<gg, 256, GSMEM>>>(p_xr, p_w + 2ULL * CC * CC, p_r);

    // 4. WKV chunked scan (3 passes) + sigmoid fusion (outputs fp16)
    {
        int n1 = NCHK * NBC;  // 262144
        wkv_pass1<<<(n1 + 255) / 256, 256>>>(p_k, p_v, td);
        wkv_pass2<<<(NBC + 255) / 256, 256>>>(td);
        wkv_pass3<<<(n1 + 255) / 256, 256>>>(p_k, p_v, p_r, td, tf, p_s);
    }

    // 5. output GEMM into d_out
    gemm_f16<<<gg, 256, GSMEM>>>(p_s, p_w + 3ULL * CC * CC, out);
}

// round 8
// speedup vs baseline: 3.7841x; 1.0488x over previous
#include <cuda_runtime.h>
#include <cuda_fp16.h>
#include <cstdint>

// Problem dims
#define BB 8
#define TT 1024
#define CC 2048
#define MM (BB * TT)          // 8192
#define NELEM (BB * TT * CC)  // 16,777,216

// WKV chunking
#define NCHK 32
#define LCHK (TT / NCHK)      // 32
#define NBC (BB * CC)         // 16384

// GEMM tiling (HMMA mma.sync, fp16, 3-stage pipeline)
#define BM 128
#define BN 128
#define BKK 32
#define NITER (CC / BKK)      // 64
#define SROWB 80
#define TILEB (128 * SROWB)   // 10240
#define STAGEB (2 * TILEB)    // 20480 (A + B)
#define NSTAGE 3
#define GSMEM (NSTAGE * STAGEB)  // 61440

// ---------------------------------------------------------------------------
// Scratch (static device globals; no allocation anywhere)
// ---------------------------------------------------------------------------
__device__ __half g_xk16[NELEM], g_xv16[NELEM], g_xr16[NELEM];
__device__ __half g_w16[4ULL * CC * CC];
__device__ float g_k[NELEM], g_v[NELEM], g_r[NELEM];
__device__ __half g_s16[NELEM];
// wkv chunk-scan scratch
__device__ float g_sv[NCHK * NBC], g_sd[NCHK * NBC], g_sm[NCHK * NBC];
__device__ float g_inum[NCHK * NBC], g_iden[NCHK * NBC], g_imx[NCHK * NBC];

// ---------------------------------------------------------------------------
// Helpers
// ---------------------------------------------------------------------------
__device__ __forceinline__ uint32_t smem_u32(const void* p) {
    uint32_t a;
    asm("{ .reg .u64 t; cvta.to.shared.u64 t, %1; cvt.u32.u64 %0, t; }"
        : "=r"(a) : "l"(p));
    return a;
}
__device__ __forceinline__ void cp_async16(uint32_t saddr, const void* gaddr) {
    asm volatile("cp.async.cg.shared.global [%0], [%1], 16;"
                 :: "r"(saddr), "l"(gaddr));
}
__device__ __forceinline__ void cp_commit() { asm volatile("cp.async.commit_group;"); }
__device__ __forceinline__ void cp_wait1() { asm volatile("cp.async.wait_group 1;"); }
__device__ __forceinline__ void cp_wait0() { asm volatile("cp.async.wait_group 0;"); }

__device__ __forceinline__ void ldsm_x4(uint32_t addr, uint32_t& r0, uint32_t& r1,
                                        uint32_t& r2, uint32_t& r3) {
    asm volatile("ldmatrix.sync.aligned.m8n8.x4.shared.b16 {%0,%1,%2,%3}, [%4];"
                 : "=r"(r0), "=r"(r1), "=r"(r2), "=r"(r3) : "r"(addr));
}
__device__ __forceinline__ void mma_f16(float* c, const uint32_t* a, const uint32_t* b) {
    asm volatile(
        "mma.sync.aligned.m16n8k16.row.col.f32.f16.f16.f32 "
        "{%0,%1,%2,%3}, {%4,%5,%6,%7}, {%8,%9}, {%0,%1,%2,%3};"
        : "+f"(c[0]), "+f"(c[1]), "+f"(c[2]), "+f"(c[3])
        : "r"(a[0]), "r"(a[1]), "r"(a[2]), "r"(a[3]), "r"(b[0]), "r"(b[1]));
}

__device__ __forceinline__ void store_h4(__half* __restrict__ dst, size_t base, float4 v) {
    __half2 a = __floats2half2_rn(v.x, v.y);
    __half2 b = __floats2half2_rn(v.z, v.w);
    *reinterpret_cast<__half2*>(dst + base)     = a;
    *reinterpret_cast<__half2*>(dst + base + 2) = b;
}

// ---------------------------------------------------------------------------
// Kernel: fp32 -> fp16 convert, all 4 weight matrices in one launch
// ---------------------------------------------------------------------------
__global__ void cvt16_all(const float4* __restrict__ s0,
                          const float4* __restrict__ s1,
                          const float4* __restrict__ s2,
                          const float4* __restrict__ s3,
                          __half* __restrict__ dst) {
    const int n4 = CC * CC / 4;
    int i = blockIdx.x * blockDim.x + threadIdx.x;
    if (i >= 4 * n4) return;
    int m = i / n4;
    int o = i - m * n4;
    const float4* src = (m == 0) ? s0 : (m == 1) ? s1 : (m == 2) ? s2 : s3;
    store_h4(dst, (size_t)i * 4, src[o]);
}

// ---------------------------------------------------------------------------
// Kernel: time-shift mixing fused with fp16 convert
// ---------------------------------------------------------------------------
__global__ void mix16_kernel(const float4* __restrict__ x4,
                             const float4* __restrict__ tmk4,
                             const float4* __restrict__ tmv4,
                             const float4* __restrict__ tmr4) {
    const int C4 = CC / 4;
    int i = blockIdx.x * blockDim.x + threadIdx.x;
    if (i >= NELEM / 4) return;
    int c4 = i % C4;
    int t = (i / C4) % TT;

    float4 xc = x4[i];
    float4 xs = make_float4(0.f, 0.f, 0.f, 0.f);
    if (t > 0) xs = x4[i - C4];

    float4 mk = tmk4[c4], mv = tmv4[c4], mr = tmr4[c4];
    float4 ok, ov, orr;
    ok.x  = xc.x * mk.x + xs.x * (1.f - mk.x);
    ok.y  = xc.y * mk.y + xs.y * (1.f - mk.y);
    ok.z  = xc.z * mk.z + xs.z * (1.f - mk.z);
    ok.w  = xc.w * mk.w + xs.w * (1.f - mk.w);
    ov.x  = xc.x * mv.x + xs.x * (1.f - mv.x);
    ov.y  = xc.y * mv.y + xs.y * (1.f - mv.y);
    ov.z  = xc.z * mv.z + xs.z * (1.f - mv.z);
    ov.w  = xc.w * mv.w + xs.w * (1.f - mv.w);
    orr.x = xc.x * mr.x + xs.x * (1.f - mr.x);
    orr.y = xc.y * mr.y + xs.y * (1.f - mr.y);
    orr.z = xc.z * mr.z + xs.z * (1.f - mr.z);
    orr.w = xc.w * mr.w + xs.w * (1.f - mr.w);

    size_t base = (size_t)i * 4;
    store_h4(g_xk16, base, ok);
    store_h4(g_xv16, base, ov);
    store_h4(g_xr16, base, orr);
}

// ---------------------------------------------------------------------------
// Kernel: fp16 HMMA GEMM, 3-stage cp.async pipeline, ONE sync per k-iter.
// 128x128 CTA, 64x32 warp tile, BK=32, 2 CTAs/SM.
// ---------------------------------------------------------------------------
__global__ __launch_bounds__(256, 2)
void gemm_f16(const __half* __restrict__ A,
              const __half* __restrict__ B,
              float* __restrict__ C) {
    extern __shared__ __align__(128) char smem[];
    const uint32_t sb = smem_u32(smem);
    const int tid = threadIdx.x;
    const int wid = tid >> 5;
    const int lane = tid & 31;
    const int wm = wid >> 2;
    const int wn = wid & 3;
    const int rowBase = blockIdx.y * BM;
    const int colBase = blockIdx.x * BN;
    const int warpRow = wm * 64;
    const int warpCol = wn * 32;

    const uint32_t OF_A = 0, OF_B = TILEB;

    auto issue_stage = [&](int buf, int k0) {
        uint32_t sbase = sb + buf * STAGEB;
#pragma unroll
        for (int it = 0; it < 2; it++) {
            int idx = tid + it * 256;
            int r = idx >> 2, c = idx & 3;
            uint32_t so = (uint32_t)(r * SROWB + c * 16);
            size_t gA = (size_t)(rowBase + r) * CC + k0 + c * 8;
            size_t gB = (size_t)(colBase + r) * CC + k0 + c * 8;
            cp_async16(sbase + OF_A + so, A + gA);
            cp_async16(sbase + OF_B + so, B + gB);
        }
        cp_commit();
    };

    float acc[4][4][4];
#pragma unroll
    for (int i = 0; i < 4; i++)
#pragma unroll
        for (int j = 0; j < 4; j++)
#pragma unroll
            for (int q = 0; q < 4; q++) acc[i][j][q] = 0.f;

    const uint32_t aLaneOff =
        (uint32_t)((warpRow + (lane & 15)) * SROWB + (lane >> 4) * 16);
    const int bg = lane >> 3, bw = lane & 7;
    const uint32_t bLaneOff =
        (uint32_t)((warpCol + (bg >> 1) * 8 + bw) * SROWB + (bg & 1) * 16);

    issue_stage(0, 0);
    issue_stage(1, BKK);

    int buf = 0, nbuf = 2;  // buf = stage to consume; nbuf = stage to fill
#pragma unroll 1
    for (int j = 0; j < NITER; j++) {
        // stage j has arrived when <=1 newer group outstanding
        if (j + 2 < NITER) cp_wait1(); else cp_wait0();
        __syncthreads();   // all warps finished consuming stage j-1 (buf == nbuf's previous use)
        if (j + 2 < NITER) {
            issue_stage(nbuf, (j + 2) * BKK);
        }

        const uint32_t sbase = sb + buf * STAGEB;
#pragma unroll
        for (int kk = 0; kk < 2; kk++) {
            const uint32_t kOff = kk * 32;
            uint32_t ah[4][4], bx[4][2];
#pragma unroll
            for (int i = 0; i < 4; i++) {
                uint32_t ad = sbase + OF_A + aLaneOff + i * 16 * SROWB + kOff;
                ldsm_x4(ad, ah[i][0], ah[i][1], ah[i][2], ah[i][3]);
            }
#pragma unroll
            for (int jp = 0; jp < 2; jp++) {
                uint32_t bd = sbase + OF_B + bLaneOff + jp * 16 * SROWB + kOff;
                ldsm_x4(bd, bx[jp * 2][0], bx[jp * 2][1],
                        bx[jp * 2 + 1][0], bx[jp * 2 + 1][1]);
            }
#pragma unroll
            for (int i = 0; i < 4; i++)
#pragma unroll
                for (int jj = 0; jj < 4; jj++) mma_f16(acc[i][jj], ah[i], bx[jj]);
        }
        buf = (buf == NSTAGE - 1) ? 0 : buf + 1;
        nbuf = (nbuf == NSTAGE - 1) ? 0 : nbuf + 1;
    }

    const int er = lane >> 2, ec = (lane & 3) * 2;
#pragma unroll
    for (int i = 0; i < 4; i++) {
#pragma unroll
        for (int jj = 0; jj < 4; jj++) {
            size_t row0 = (size_t)(rowBase + warpRow + i * 16 + er);
            size_t col = (size_t)(colBase + warpCol + jj * 8 + ec);
            float2 v0 = make_float2(acc[i][jj][0], acc[i][jj][1]);
            float2 v1 = make_float2(acc[i][jj][2], acc[i][jj][3]);
            *reinterpret_cast<float2*>(C + row0 * CC + col) = v0;
            *reinterpret_cast<float2*>(C + (row0 + 8) * CC + col) = v1;
        }
    }
}

// ---------------------------------------------------------------------------
// WKV pass 1: per-(chunk, b, c) local stabilized sums (zero initial state)
// ---------------------------------------------------------------------------
__global__ void wkv_pass1(const float* __restrict__ k,
                          const float* __restrict__ v,
                          const float* __restrict__ time_decay) {
    int idx = blockIdx.x * blockDim.x + threadIdx.x;
    if (idx >= NCHK * NBC) return;
    int c = idx % CC;
    int b = (idx / CC) % BB;
    int chunk = idx / NBC;

    const float w = -__expf(time_decay[c]);
    float s_v = 0.f, s_d = 0.f, m = -1e38f;
    size_t base = ((size_t)b * TT + chunk * LCHK) * CC + c;

#pragma unroll 4
    for (int t = 0; t < LCHK; t++) {
        size_t g = base + (size_t)t * CC;
        float kt = k[g];
        float vt = v[g];
        float mw = m + w;
        float mn = fmaxf(mw, kt);
        float e1 = __expf(mw - mn);
        float e2 = __expf(kt - mn);
        s_v = e1 * s_v + e2 * vt;
        s_d = e1 * s_d + e2;
        m = mn;
    }
    g_sv[idx] = s_v;
    g_sd[idx] = s_d;
    g_sm[idx] = m;
}

// ---------------------------------------------------------------------------
// WKV pass 2: sequential prefix over chunks per (b, c)
// ---------------------------------------------------------------------------
__global__ void wkv_pass2(const float* __restrict__ time_decay) {
    int idx = blockIdx.x * blockDim.x + threadIdx.x;
    if (idx >= NBC) return;
    int c = idx % CC;
    const float w = -__expf(time_decay[c]);
    const float Lw = (float)LCHK * w;

    float num = 0.f, den = 0.f, mx = -1e38f;
#pragma unroll
    for (int ch = 0; ch < NCHK; ch++) {
        size_t o = (size_t)ch * NBC + idx;
        g_inum[o] = num;
        g_iden[o] = den;
        g_imx[o] = mx;
        float ms = g_sm[o];
        float mo = mx + Lw;
        float mn = fmaxf(mo, ms);
        float e1 = __expf(mo - mn);
        float e2 = __expf(ms - mn);
        num = e1 * num + e2 * g_sv[o];
        den = e1 * den + e2 * g_sd[o];
        mx = mn;
    }
}

// ---------------------------------------------------------------------------
// WKV pass 3: replay reference step inside each chunk; fuse sigmoid(r), fp16
// ---------------------------------------------------------------------------
__global__ void wkv_pass3(const float* __restrict__ k,
                          const float* __restrict__ v,
                          const float* __restrict__ r,
                          const float* __restrict__ time_decay,
                          const float* __restrict__ time_first,
                          __half* __restrict__ s) {
    int idx = blockIdx.x * blockDim.x + threadIdx.x;
    if (idx >= NCHK * NBC) return;
    int c = idx % CC;
    int b = (idx / CC) % BB;
    int chunk = idx / NBC;

    const float w = -__expf(time_decay[c]);
    const float u = time_first[c];

    float num = g_inum[idx];
    float den = g_iden[idx];
    float mx  = g_imx[idx];
    size_t base = ((size_t)b * TT + chunk * LCHK) * CC + c;

#pragma unroll 2
    for (int t = 0; t < LCHK; t++) {
        size_t g = base + (size_t)t * CC;
        float kt = k[g];
        float vt = v[g];
        float rv = r[g];

        float ku = kt + u;
        float max_out = fmaxf(mx, ku);
        float e1 = __expf(mx - max_out);
        float e2 = __expf(ku - max_out);
        float o = __fdividef(e1 * num + e2 * vt, e1 * den + e2);

        float mw = mx + w;
        float max_st = fmaxf(mw, kt);
        float e1s = __expf(mw - max_st);
        float e2s = __expf(kt - max_st);
        num = e1s * num + e2s * vt;
        den = e1s * den + e2s;
        mx = max_st;

        float sr = __fdividef(1.f, 1.f + __expf(-rv));
        s[g] = __float2half_rn(sr * o);
    }
}

// ---------------------------------------------------------------------------
// Launch
// ---------------------------------------------------------------------------
extern "C" void kernel_launch(void* const* d_in, const int* in_sizes, int n_in,
                              void* d_out, int out_size) {
    const float* x   = (const float*)d_in[0];
    const float* td  = (const float*)d_in[1];
    const float* tf  = (const float*)d_in[2];
    const float* tmk = (const float*)d_in[3];
    const float* tmv = (const float*)d_in[4];
    const float* tmr = (const float*)d_in[5];
    const float* Wk  = (const float*)d_in[6];
    const float* Wv  = (const float*)d_in[7];
    const float* Wr  = (const float*)d_in[8];
    const float* Wo  = (const float*)d_in[9];
    float* out = (float*)d_out;

    static bool inited = false;
    static __half *p_xk, *p_xv, *p_xr, *p_w, *p_s;
    static float *p_k, *p_v, *p_r;
    if (!inited) {
        cudaGetSymbolAddress((void**)&p_xk, g_xk16);
        cudaGetSymbolAddress((void**)&p_xv, g_xv16);
        cudaGetSymbolAddress((void**)&p_xr, g_xr16);
        cudaGetSymbolAddress((void**)&p_w,  g_w16);
        cudaGetSymbolAddress((void**)&p_k,  g_k);
        cudaGetSymbolAddress((void**)&p_v,  g_v);
        cudaGetSymbolAddress((void**)&p_r,  g_r);
        cudaGetSymbolAddress((void**)&p_s,  g_s16);
        cudaFuncSetAttribute(gemm_f16,
                             cudaFuncAttributeMaxDynamicSharedMemorySize, GSMEM);
        inited = true;
    }

    // 1. convert the 4 weight matrices to fp16 (one launch)
    {
        int n = 4 * CC * CC / 4;
        cvt16_all<<<(n + 255) / 256, 256>>>((const float4*)Wk, (const float4*)Wv,
                                            (const float4*)Wr, (const float4*)Wo, p_w);
    }

    // 2. time-shift mixing + fp16 convert
    {
        int n4 = NELEM / 4;
        mix16_kernel<<<(n4 + 255) / 256, 256>>>(
            (const float4*)x, (const float4*)tmk, (const float4*)tmv, (const float4*)tmr);
    }

    // 3. projection GEMMs (fp16 HMMA)
    dim3 gg(CC / BN, MM / BM);  // (16, 64)
    gemm_f16<<<gg, 256, GSMEM>>>(p_xk, p_w + 0ULL * CC * CC, p_k);
    gemm_f16<<<gg, 256, GSMEM>>>(p_xv, p_w + 1ULL * CC * CC, p_v);
    gemm_f16<<<gg, 256, GSMEM>>>(p_xr, p_w + 2ULL * CC * CC, p_r);

    // 4. WKV chunked scan (3 passes) + sigmoid fusion (outputs fp16)
    {
        int n1 = NCHK * NBC;  // 524288
        wkv_pass1<<<(n1 + 255) / 256, 256>>>(p_k, p_v, td);
        wkv_pass2<<<(NBC + 255) / 256, 256>>>(td);
        wkv_pass3<<<(n1 + 255) / 256, 256>>>(p_k, p_v, p_r, td, tf, p_s);
    }

    // 5. output GEMM into d_out
    gemm_f16<<<gg, 256, GSMEM>>>(p_s, p_w + 3ULL * CC * CC, out);
}

// round 9
// speedup vs baseline: 4.4039x; 1.1638x over previous
#include <cuda_runtime.h>
#include <cuda_fp16.h>
#include <cstdint>

// Problem dims
#define BB 8
#define TT 1024
#define CC 2048
#define MM (BB * TT)          // 8192
#define NELEM (BB * TT * CC)  // 16,777,216

// WKV chunking
#define NCHK 32
#define LCHK (TT / NCHK)      // 32
#define NBC (BB * CC)         // 16384

// GEMM tiling (HMMA mma.sync, fp16, BK=64, 3-stage pipeline)
#define BM 128
#define BN 128
#define BKK 64
#define NITER (CC / BKK)      // 32
#define SROWB 144             // 64 fp16 = 128B + 16B pad (9 chunks: conflict-free)
#define TILEB (128 * SROWB)   // 18432
#define STAGEB (2 * TILEB)    // 36864 (A + B)
#define NSTAGE 3
#define GSMEM (NSTAGE * STAGEB)  // 110592

// ---------------------------------------------------------------------------
// Scratch (static device globals; no allocation anywhere)
// ---------------------------------------------------------------------------
__device__ __half g_xk16[NELEM], g_xv16[NELEM], g_xr16[NELEM];
__device__ __half g_w16[4ULL * CC * CC];
__device__ float g_k[NELEM], g_v[NELEM], g_r[NELEM];
__device__ __half g_s16[NELEM];
// wkv chunk-scan scratch
__device__ float g_sv[NCHK * NBC], g_sd[NCHK * NBC], g_sm[NCHK * NBC];
__device__ float g_inum[NCHK * NBC], g_iden[NCHK * NBC], g_imx[NCHK * NBC];

// ---------------------------------------------------------------------------
// Helpers
// ---------------------------------------------------------------------------
__device__ __forceinline__ uint32_t smem_u32(const void* p) {
    uint32_t a;
    asm("{ .reg .u64 t; cvta.to.shared.u64 t, %1; cvt.u32.u64 %0, t; }"
        : "=r"(a) : "l"(p));
    return a;
}
__device__ __forceinline__ void cp_async16(uint32_t saddr, const void* gaddr) {
    asm volatile("cp.async.cg.shared.global [%0], [%1], 16;"
                 :: "r"(saddr), "l"(gaddr));
}
__device__ __forceinline__ void cp_commit() { asm volatile("cp.async.commit_group;"); }
__device__ __forceinline__ void cp_wait1() { asm volatile("cp.async.wait_group 1;"); }
__device__ __forceinline__ void cp_wait0() { asm volatile("cp.async.wait_group 0;"); }

__device__ __forceinline__ void ldsm_x4(uint32_t addr, uint32_t& r0, uint32_t& r1,
                                        uint32_t& r2, uint32_t& r3) {
    asm volatile("ldmatrix.sync.aligned.m8n8.x4.shared.b16 {%0,%1,%2,%3}, [%4];"
                 : "=r"(r0), "=r"(r1), "=r"(r2), "=r"(r3) : "r"(addr));
}
__device__ __forceinline__ void mma_f16(float* c, const uint32_t* a, const uint32_t* b) {
    asm volatile(
        "mma.sync.aligned.m16n8k16.row.col.f32.f16.f16.f32 "
        "{%0,%1,%2,%3}, {%4,%5,%6,%7}, {%8,%9}, {%0,%1,%2,%3};"
        : "+f"(c[0]), "+f"(c[1]), "+f"(c[2]), "+f"(c[3])
        : "r"(a[0]), "r"(a[1]), "r"(a[2]), "r"(a[3]), "r"(b[0]), "r"(b[1]));
}

__device__ __forceinline__ void store_h4(__half* __restrict__ dst, size_t base, float4 v) {
    __half2 a = __floats2half2_rn(v.x, v.y);
    __half2 b = __floats2half2_rn(v.z, v.w);
    *reinterpret_cast<__half2*>(dst + base)     = a;
    *reinterpret_cast<__half2*>(dst + base + 2) = b;
}

// ---------------------------------------------------------------------------
// Kernel: fp32 -> fp16 convert, all 4 weight matrices in one launch
// ---------------------------------------------------------------------------
__global__ void cvt16_all(const float4* __restrict__ s0,
                          const float4* __restrict__ s1,
                          const float4* __restrict__ s2,
                          const float4* __restrict__ s3,
                          __half* __restrict__ dst) {
    const int n4 = CC * CC / 4;
    int i = blockIdx.x * blockDim.x + threadIdx.x;
    if (i >= 4 * n4) return;
    int m = i / n4;
    int o = i - m * n4;
    const float4* src = (m == 0) ? s0 : (m == 1) ? s1 : (m == 2) ? s2 : s3;
    store_h4(dst, (size_t)i * 4, src[o]);
}

// ---------------------------------------------------------------------------
// Kernel: time-shift mixing fused with fp16 convert
// ---------------------------------------------------------------------------
__global__ void mix16_kernel(const float4* __restrict__ x4,
                             const float4* __restrict__ tmk4,
                             const float4* __restrict__ tmv4,
                             const float4* __restrict__ tmr4) {
    const int C4 = CC / 4;
    int i = blockIdx.x * blockDim.x + threadIdx.x;
    if (i >= NELEM / 4) return;
    int c4 = i % C4;
    int t = (i / C4) % TT;

    float4 xc = x4[i];
    float4 xs = make_float4(0.f, 0.f, 0.f, 0.f);
    if (t > 0) xs = x4[i - C4];

    float4 mk = tmk4[c4], mv = tmv4[c4], mr = tmr4[c4];
    float4 ok, ov, orr;
    ok.x  = xc.x * mk.x + xs.x * (1.f - mk.x);
    ok.y  = xc.y * mk.y + xs.y * (1.f - mk.y);
    ok.z  = xc.z * mk.z + xs.z * (1.f - mk.z);
    ok.w  = xc.w * mk.w + xs.w * (1.f - mk.w);
    ov.x  = xc.x * mv.x + xs.x * (1.f - mv.x);
    ov.y  = xc.y * mv.y + xs.y * (1.f - mv.y);
    ov.z  = xc.z * mv.z + xs.z * (1.f - mv.z);
    ov.w  = xc.w * mv.w + xs.w * (1.f - mv.w);
    orr.x = xc.x * mr.x + xs.x * (1.f - mr.x);
    orr.y = xc.y * mr.y + xs.y * (1.f - mr.y);
    orr.z = xc.z * mr.z + xs.z * (1.f - mr.z);
    orr.w = xc.w * mr.w + xs.w * (1.f - mr.w);

    size_t base = (size_t)i * 4;
    store_h4(g_xk16, base, ok);
    store_h4(g_xv16, base, ov);
    store_h4(g_xr16, base, orr);
}

// ---------------------------------------------------------------------------
// Kernel: fp16 HMMA GEMM, BK=64, 3-stage cp.async pipeline, one sync/iter.
// gridDim.z selects (A, B, C) triple so 3 projections fuse into one launch.
// ---------------------------------------------------------------------------
__global__ __launch_bounds__(256, 2)
void gemm_f16(const __half* __restrict__ A0, const __half* __restrict__ A1,
              const __half* __restrict__ A2, const __half* __restrict__ Bbase,
              float* __restrict__ C0, float* __restrict__ C1,
              float* __restrict__ C2) {
    extern __shared__ __align__(128) char smem[];
    const uint32_t sb = smem_u32(smem);
    const int z = blockIdx.z;
    const __half* A = (z == 0) ? A0 : (z == 1) ? A1 : A2;
    const __half* B = Bbase + (size_t)z * CC * CC;
    float* C = (z == 0) ? C0 : (z == 1) ? C1 : C2;

    const int tid = threadIdx.x;
    const int wid = tid >> 5;
    const int lane = tid & 31;
    const int wm = wid >> 2;
    const int wn = wid & 3;
    const int rowBase = blockIdx.y * BM;
    const int colBase = blockIdx.x * BN;
    const int warpRow = wm * 64;
    const int warpCol = wn * 32;

    const uint32_t OF_A = 0, OF_B = TILEB;

    auto issue_stage = [&](int buf, int k0) {
        uint32_t sbase = sb + buf * STAGEB;
#pragma unroll
        for (int it = 0; it < 4; it++) {
            int idx = tid + it * 256;
            int r = idx >> 3, c = idx & 7;
            uint32_t so = (uint32_t)(r * SROWB + c * 16);
            size_t gA = (size_t)(rowBase + r) * CC + k0 + c * 8;
            size_t gB = (size_t)(colBase + r) * CC + k0 + c * 8;
            cp_async16(sbase + OF_A + so, A + gA);
            cp_async16(sbase + OF_B + so, B + gB);
        }
        cp_commit();
    };

    float acc[4][4][4];
#pragma unroll
    for (int i = 0; i < 4; i++)
#pragma unroll
        for (int j = 0; j < 4; j++)
#pragma unroll
            for (int q = 0; q < 4; q++) acc[i][j][q] = 0.f;

    const uint32_t aLaneOff =
        (uint32_t)((warpRow + (lane & 15)) * SROWB + (lane >> 4) * 16);
    const int bg = lane >> 3, bw = lane & 7;
    const uint32_t bLaneOff =
        (uint32_t)((warpCol + (bg >> 1) * 8 + bw) * SROWB + (bg & 1) * 16);

    issue_stage(0, 0);
    issue_stage(1, BKK);

    int buf = 0, nbuf = 2;
#pragma unroll 1
    for (int j = 0; j < NITER; j++) {
        if (j + 2 < NITER) cp_wait1(); else cp_wait0();
        __syncthreads();
        if (j + 2 < NITER) issue_stage(nbuf, (j + 2) * BKK);

        const uint32_t sbase = sb + buf * STAGEB;
#pragma unroll
        for (int kk = 0; kk < 4; kk++) {
            const uint32_t kOff = kk * 32;
            uint32_t ah[4][4], bx[4][2];
#pragma unroll
            for (int i = 0; i < 4; i++) {
                uint32_t ad = sbase + OF_A + aLaneOff + i * 16 * SROWB + kOff;
                ldsm_x4(ad, ah[i][0], ah[i][1], ah[i][2], ah[i][3]);
            }
#pragma unroll
            for (int jp = 0; jp < 2; jp++) {
                uint32_t bd = sbase + OF_B + bLaneOff + jp * 16 * SROWB + kOff;
                ldsm_x4(bd, bx[jp * 2][0], bx[jp * 2][1],
                        bx[jp * 2 + 1][0], bx[jp * 2 + 1][1]);
            }
#pragma unroll
            for (int i = 0; i < 4; i++)
#pragma unroll
                for (int jj = 0; jj < 4; jj++) mma_f16(acc[i][jj], ah[i], bx[jj]);
        }
        buf = (buf == NSTAGE - 1) ? 0 : buf + 1;
        nbuf = (nbuf == NSTAGE - 1) ? 0 : nbuf + 1;
    }

    const int er = lane >> 2, ec = (lane & 3) * 2;
#pragma unroll
    for (int i = 0; i < 4; i++) {
#pragma unroll
        for (int jj = 0; jj < 4; jj++) {
            size_t row0 = (size_t)(rowBase + warpRow + i * 16 + er);
            size_t col = (size_t)(colBase + warpCol + jj * 8 + ec);
            float2 v0 = make_float2(acc[i][jj][0], acc[i][jj][1]);
            float2 v1 = make_float2(acc[i][jj][2], acc[i][jj][3]);
            *reinterpret_cast<float2*>(C + row0 * CC + col) = v0;
            *reinterpret_cast<float2*>(C + (row0 + 8) * CC + col) = v1;
        }
    }
}

// ---------------------------------------------------------------------------
// WKV pass 1: per-(chunk, b, c) local stabilized sums (zero initial state)
// ---------------------------------------------------------------------------
__global__ void wkv_pass1(const float* __restrict__ k,
                          const float* __restrict__ v,
                          const float* __restrict__ time_decay) {
    int idx = blockIdx.x * blockDim.x + threadIdx.x;
    if (idx >= NCHK * NBC) return;
    int c = idx % CC;
    int b = (idx / CC) % BB;
    int chunk = idx / NBC;

    const float w = -__expf(time_decay[c]);
    float s_v = 0.f, s_d = 0.f, m = -1e38f;
    size_t base = ((size_t)b * TT + chunk * LCHK) * CC + c;

#pragma unroll 4
    for (int t = 0; t < LCHK; t++) {
        size_t g = base + (size_t)t * CC;
        float kt = k[g];
        float vt = v[g];
        float mw = m + w;
        float mn = fmaxf(mw, kt);
        float e1 = __expf(mw - mn);
        float e2 = __expf(kt - mn);
        s_v = e1 * s_v + e2 * vt;
        s_d = e1 * s_d + e2;
        m = mn;
    }
    g_sv[idx] = s_v;
    g_sd[idx] = s_d;
    g_sm[idx] = m;
}

// ---------------------------------------------------------------------------
// WKV pass 2: sequential prefix over chunks per (b, c)
// ---------------------------------------------------------------------------
__global__ void wkv_pass2(const float* __restrict__ time_decay) {
    int idx = blockIdx.x * blockDim.x + threadIdx.x;
    if (idx >= NBC) return;
    int c = idx % CC;
    const float w = -__expf(time_decay[c]);
    const float Lw = (float)LCHK * w;

    float num = 0.f, den = 0.f, mx = -1e38f;
#pragma unroll
    for (int ch = 0; ch < NCHK; ch++) {
        size_t o = (size_t)ch * NBC + idx;
        g_inum[o] = num;
        g_iden[o] = den;
        g_imx[o] = mx;
        float ms = g_sm[o];
        float mo = mx + Lw;
        float mn = fmaxf(mo, ms);
        float e1 = __expf(mo - mn);
        float e2 = __expf(ms - mn);
        num = e1 * num + e2 * g_sv[o];
        den = e1 * den + e2 * g_sd[o];
        mx = mn;
    }
}

// ---------------------------------------------------------------------------
// WKV pass 3: replay reference step inside each chunk; fuse sigmoid(r), fp16
// ---------------------------------------------------------------------------
__global__ void wkv_pass3(const float* __restrict__ k,
                          const float* __restrict__ v,
                          const float* __restrict__ r,
                          const float* __restrict__ time_decay,
                          const float* __restrict__ time_first,
                          __half* __restrict__ s) {
    int idx = blockIdx.x * blockDim.x + threadIdx.x;
    if (idx >= NCHK * NBC) return;
    int c = idx % CC;
    int b = (idx / CC) % BB;
    int chunk = idx / NBC;

    const float w = -__expf(time_decay[c]);
    const float u = time_first[c];

    float num = g_inum[idx];
    float den = g_iden[idx];
    float mx  = g_imx[idx];
    size_t base = ((size_t)b * TT + chunk * LCHK) * CC + c;

#pragma unroll 2
    for (int t = 0; t < LCHK; t++) {
        size_t g = base + (size_t)t * CC;
        float kt = k[g];
        float vt = v[g];
        float rv = r[g];

        float ku = kt + u;
        float max_out = fmaxf(mx, ku);
        float e1 = __expf(mx - max_out);
        float e2 = __expf(ku - max_out);
        float o = __fdividef(e1 * num + e2 * vt, e1 * den + e2);

        float mw = mx + w;
        float max_st = fmaxf(mw, kt);
        float e1s = __expf(mw - max_st);
        float e2s = __expf(kt - max_st);
        num = e1s * num + e2s * vt;
        den = e1s * den + e2s;
        mx = max_st;

        float sr = __fdividef(1.f, 1.f + __expf(-rv));
        s[g] = __float2half_rn(sr * o);
    }
}

// ---------------------------------------------------------------------------
// Launch
// ---------------------------------------------------------------------------
extern "C" void kernel_launch(void* const* d_in, const int* in_sizes, int n_in,
                              void* d_out, int out_size) {
    const float* x   = (const float*)d_in[0];
    const float* td  = (const float*)d_in[1];
    const float* tf  = (const float*)d_in[2];
    const float* tmk = (const float*)d_in[3];
    const float* tmv = (const float*)d_in[4];
    const float* tmr = (const float*)d_in[5];
    const float* Wk  = (const float*)d_in[6];
    const float* Wv  = (const float*)d_in[7];
    const float* Wr  = (const float*)d_in[8];
    const float* Wo  = (const float*)d_in[9];
    float* out = (float*)d_out;

    static bool inited = false;
    static __half *p_xk, *p_xv, *p_xr, *p_w, *p_s;
    static float *p_k, *p_v, *p_r;
    if (!inited) {
        cudaGetSymbolAddress((void**)&p_xk, g_xk16);
        cudaGetSymbolAddress((void**)&p_xv, g_xv16);
        cudaGetSymbolAddress((void**)&p_xr, g_xr16);
        cudaGetSymbolAddress((void**)&p_w,  g_w16);
        cudaGetSymbolAddress((void**)&p_k,  g_k);
        cudaGetSymbolAddress((void**)&p_v,  g_v);
        cudaGetSymbolAddress((void**)&p_r,  g_r);
        cudaGetSymbolAddress((void**)&p_s,  g_s16);
        cudaFuncSetAttribute(gemm_f16,
                             cudaFuncAttributeMaxDynamicSharedMemorySize, GSMEM);
        inited = true;
    }

    // 1. convert the 4 weight matrices to fp16 (one launch)
    {
        int n = 4 * CC * CC / 4;
        cvt16_all<<<(n + 255) / 256, 256>>>((const float4*)Wk, (const float4*)Wv,
                                            (const float4*)Wr, (const float4*)Wo, p_w);
    }

    // 2. time-shift mixing + fp16 convert
    {
        int n4 = NELEM / 4;
        mix16_kernel<<<(n4 + 255) / 256, 256>>>(
            (const float4*)x, (const float4*)tmk, (const float4*)tmv, (const float4*)tmr);
    }

    // 3. fused projection GEMMs: one launch, z picks (xk,Wk,k)/(xv,Wv,v)/(xr,Wr,r)
    {
        dim3 gg(CC / BN, MM / BM, 3);  // (16, 64, 3)
        gemm_f16<<<gg, 256, GSMEM>>>(p_xk, p_xv, p_xr, p_w, p_k, p_v, p_r);
    }

    // 4. WKV chunked scan (3 passes) + sigmoid fusion (outputs fp16)
    {
        int n1 = NCHK * NBC;  // 524288
        wkv_pass1<<<(n1 + 255) / 256, 256>>>(p_k, p_v, td);
        wkv_pass2<<<(NBC + 255) / 256, 256>>>(td);
        wkv_pass3<<<(n1 + 255) / 256, 256>>>(p_k, p_v, p_r, td, tf, p_s);
    }

    // 5. output GEMM into d_out
    {
        dim3 gg(CC / BN, MM / BM, 1);
        gemm_f16<<<gg, 256, GSMEM>>>(p_s, p_s, p_s, p_w + 3ULL * CC * CC,
                                     out, out, out);
    }
}

// round 10
// speedup vs baseline: 4.4537x; 1.0113x over previous
#include <cuda_runtime.h>
#include <cuda_fp16.h>
#include <cstdint>

// Problem dims
#define BB 8
#define TT 1024
#define CC 2048
#define MM (BB * TT)          // 8192
#define NELEM (BB * TT * CC)  // 16,777,216

// WKV chunking
#define NCHK 32
#define LCHK (TT / NCHK)      // 32
#define NBC (BB * CC)         // 16384

// GEMM tiling (HMMA mma.sync, fp16, BK=64, 3-stage pipeline)
#define BM 128
#define BN 128
#define BKK 64
#define NITER (CC / BKK)      // 32
#define SROWB 144             // 64 fp16 = 128B + 16B pad
#define TILEB (128 * SROWB)   // 18432
#define STAGEB (2 * TILEB)    // 36864 (A + B)
#define NSTAGE 3
#define GSMEM (NSTAGE * STAGEB)  // 110592

// ---------------------------------------------------------------------------
// Scratch (static device globals; no allocation anywhere)
// ---------------------------------------------------------------------------
__device__ __half g_xk16[NELEM], g_xv16[NELEM], g_xr16[NELEM];
__device__ __half g_w16[4ULL * CC * CC];
__device__ float g_k[NELEM];
__device__ __half g_v16[NELEM], g_r16[NELEM];
__device__ __half g_s16[NELEM];
// wkv chunk-scan scratch
__device__ float g_sv[NCHK * NBC], g_sd[NCHK * NBC], g_sm[NCHK * NBC];
__device__ float g_inum[NCHK * NBC], g_iden[NCHK * NBC], g_imx[NCHK * NBC];

// ---------------------------------------------------------------------------
// Helpers
// ---------------------------------------------------------------------------
__device__ __forceinline__ uint32_t smem_u32(const void* p) {
    uint32_t a;
    asm("{ .reg .u64 t; cvta.to.shared.u64 t, %1; cvt.u32.u64 %0, t; }"
        : "=r"(a) : "l"(p));
    return a;
}
__device__ __forceinline__ void cp_async16(uint32_t saddr, const void* gaddr) {
    asm volatile("cp.async.cg.shared.global [%0], [%1], 16;"
                 :: "r"(saddr), "l"(gaddr));
}
__device__ __forceinline__ void cp_commit() { asm volatile("cp.async.commit_group;"); }
__device__ __forceinline__ void cp_wait1() { asm volatile("cp.async.wait_group 1;"); }
__device__ __forceinline__ void cp_wait0() { asm volatile("cp.async.wait_group 0;"); }

__device__ __forceinline__ void ldsm_x4(uint32_t addr, uint32_t& r0, uint32_t& r1,
                                        uint32_t& r2, uint32_t& r3) {
    asm volatile("ldmatrix.sync.aligned.m8n8.x4.shared.b16 {%0,%1,%2,%3}, [%4];"
                 : "=r"(r0), "=r"(r1), "=r"(r2), "=r"(r3) : "r"(addr));
}
__device__ __forceinline__ void mma_f16(float* c, const uint32_t* a, const uint32_t* b) {
    asm volatile(
        "mma.sync.aligned.m16n8k16.row.col.f32.f16.f16.f32 "
        "{%0,%1,%2,%3}, {%4,%5,%6,%7}, {%8,%9}, {%0,%1,%2,%3};"
        : "+f"(c[0]), "+f"(c[1]), "+f"(c[2]), "+f"(c[3])
        : "r"(a[0]), "r"(a[1]), "r"(a[2]), "r"(a[3]), "r"(b[0]), "r"(b[1]));
}

__device__ __forceinline__ void store_h4(__half* __restrict__ dst, size_t base, float4 v) {
    __half2 a = __floats2half2_rn(v.x, v.y);
    __half2 b = __floats2half2_rn(v.z, v.w);
    *reinterpret_cast<__half2*>(dst + base)     = a;
    *reinterpret_cast<__half2*>(dst + base + 2) = b;
}

// ---------------------------------------------------------------------------
// Kernel: fp32 -> fp16 convert, all 4 weight matrices in one launch
// ---------------------------------------------------------------------------
__global__ void cvt16_all(const float4* __restrict__ s0,
                          const float4* __restrict__ s1,
                          const float4* __restrict__ s2,
                          const float4* __restrict__ s3,
                          __half* __restrict__ dst) {
    const int n4 = CC * CC / 4;
    int i = blockIdx.x * blockDim.x + threadIdx.x;
    if (i >= 4 * n4) return;
    int m = i / n4;
    int o = i - m * n4;
    const float4* src = (m == 0) ? s0 : (m == 1) ? s1 : (m == 2) ? s2 : s3;
    store_h4(dst, (size_t)i * 4, src[o]);
}

// ---------------------------------------------------------------------------
// Kernel: time-shift mixing fused with fp16 convert
// ---------------------------------------------------------------------------
__global__ void mix16_kernel(const float4* __restrict__ x4,
                             const float4* __restrict__ tmk4,
                             const float4* __restrict__ tmv4,
                             const float4* __restrict__ tmr4) {
    const int C4 = CC / 4;
    int i = blockIdx.x * blockDim.x + threadIdx.x;
    if (i >= NELEM / 4) return;
    int c4 = i % C4;
    int t = (i / C4) % TT;

    float4 xc = x4[i];
    float4 xs = make_float4(0.f, 0.f, 0.f, 0.f);
    if (t > 0) xs = x4[i - C4];

    float4 mk = tmk4[c4], mv = tmv4[c4], mr = tmr4[c4];
    float4 ok, ov, orr;
    ok.x  = xc.x * mk.x + xs.x * (1.f - mk.x);
    ok.y  = xc.y * mk.y + xs.y * (1.f - mk.y);
    ok.z  = xc.z * mk.z + xs.z * (1.f - mk.z);
    ok.w  = xc.w * mk.w + xs.w * (1.f - mk.w);
    ov.x  = xc.x * mv.x + xs.x * (1.f - mv.x);
    ov.y  = xc.y * mv.y + xs.y * (1.f - mv.y);
    ov.z  = xc.z * mv.z + xs.z * (1.f - mv.z);
    ov.w  = xc.w * mv.w + xs.w * (1.f - mv.w);
    orr.x = xc.x * mr.x + xs.x * (1.f - mr.x);
    orr.y = xc.y * mr.y + xs.y * (1.f - mr.y);
    orr.z = xc.z * mr.z + xs.z * (1.f - mr.z);
    orr.w = xc.w * mr.w + xs.w * (1.f - mr.w);

    size_t base = (size_t)i * 4;
    store_h4(g_xk16, base, ok);
    store_h4(g_xv16, base, ov);
    store_h4(g_xr16, base, orr);
}

// ---------------------------------------------------------------------------
// Kernel: fp16 HMMA GEMM, BK=64, 3-stage cp.async pipeline, one sync/iter.
// proj=1: gridDim.z selects (A,B,C); z==0 writes fp32 (k), z>0 fp16 (v, r).
// proj=0: single fp32 output (the final Wo GEMM into d_out).
// ---------------------------------------------------------------------------
__global__ __launch_bounds__(256, 2)
void gemm_f16(const __half* __restrict__ A0, const __half* __restrict__ A1,
              const __half* __restrict__ A2, const __half* __restrict__ Bbase,
              float* __restrict__ Cf, __half* __restrict__ Ch1,
              __half* __restrict__ Ch2, int proj) {
    extern __shared__ __align__(128) char smem[];
    const uint32_t sb = smem_u32(smem);
    const int z = blockIdx.z;
    const __half* A = (z == 0) ? A0 : (z == 1) ? A1 : A2;
    const __half* B = Bbase + (size_t)z * CC * CC;

    const int tid = threadIdx.x;
    const int wid = tid >> 5;
    const int lane = tid & 31;
    const int wm = wid >> 2;
    const int wn = wid & 3;
    const int rowBase = blockIdx.y * BM;
    const int colBase = blockIdx.x * BN;
    const int warpRow = wm * 64;
    const int warpCol = wn * 32;

    const uint32_t OF_A = 0, OF_B = TILEB;

    auto issue_stage = [&](int buf, int k0) {
        uint32_t sbase = sb + buf * STAGEB;
#pragma unroll
        for (int it = 0; it < 4; it++) {
            int idx = tid + it * 256;
            int r = idx >> 3, c = idx & 7;
            uint32_t so = (uint32_t)(r * SROWB + c * 16);
            size_t gA = (size_t)(rowBase + r) * CC + k0 + c * 8;
            size_t gB = (size_t)(colBase + r) * CC + k0 + c * 8;
            cp_async16(sbase + OF_A + so, A + gA);
            cp_async16(sbase + OF_B + so, B + gB);
        }
        cp_commit();
    };

    float acc[4][4][4];
#pragma unroll
    for (int i = 0; i < 4; i++)
#pragma unroll
        for (int j = 0; j < 4; j++)
#pragma unroll
            for (int q = 0; q < 4; q++) acc[i][j][q] = 0.f;

    const uint32_t aLaneOff =
        (uint32_t)((warpRow + (lane & 15)) * SROWB + (lane >> 4) * 16);
    const int bg = lane >> 3, bw = lane & 7;
    const uint32_t bLaneOff =
        (uint32_t)((warpCol + (bg >> 1) * 8 + bw) * SROWB + (bg & 1) * 16);

    issue_stage(0, 0);
    issue_stage(1, BKK);

    int buf = 0, nbuf = 2;
#pragma unroll 1
    for (int j = 0; j < NITER; j++) {
        if (j + 2 < NITER) cp_wait1(); else cp_wait0();
        __syncthreads();
        if (j + 2 < NITER) issue_stage(nbuf, (j + 2) * BKK);

        const uint32_t sbase = sb + buf * STAGEB;
#pragma unroll
        for (int kk = 0; kk < 4; kk++) {
            const uint32_t kOff = kk * 32;
            uint32_t ah[4][4], bx[4][2];
#pragma unroll
            for (int i = 0; i < 4; i++) {
                uint32_t ad = sbase + OF_A + aLaneOff + i * 16 * SROWB + kOff;
                ldsm_x4(ad, ah[i][0], ah[i][1], ah[i][2], ah[i][3]);
            }
#pragma unroll
            for (int jp = 0; jp < 2; jp++) {
                uint32_t bd = sbase + OF_B + bLaneOff + jp * 16 * SROWB + kOff;
                ldsm_x4(bd, bx[jp * 2][0], bx[jp * 2][1],
                        bx[jp * 2 + 1][0], bx[jp * 2 + 1][1]);
            }
#pragma unroll
            for (int i = 0; i < 4; i++)
#pragma unroll
                for (int jj = 0; jj < 4; jj++) mma_f16(acc[i][jj], ah[i], bx[jj]);
        }
        buf = (buf == NSTAGE - 1) ? 0 : buf + 1;
        nbuf = (nbuf == NSTAGE - 1) ? 0 : nbuf + 1;
    }

    const int er = lane >> 2, ec = (lane & 3) * 2;
    if (proj && z > 0) {
        // fp16 output (v or r)
        __half* Ch = (z == 1) ? Ch1 : Ch2;
#pragma unroll
        for (int i = 0; i < 4; i++) {
#pragma unroll
            for (int jj = 0; jj < 4; jj++) {
                size_t row0 = (size_t)(rowBase + warpRow + i * 16 + er);
                size_t col = (size_t)(colBase + warpCol + jj * 8 + ec);
                __half2 v0 = __floats2half2_rn(acc[i][jj][0], acc[i][jj][1]);
                __half2 v1 = __floats2half2_rn(acc[i][jj][2], acc[i][jj][3]);
                *reinterpret_cast<__half2*>(Ch + row0 * CC + col) = v0;
                *reinterpret_cast<__half2*>(Ch + (row0 + 8) * CC + col) = v1;
            }
        }
    } else {
        // fp32 output (k, or the final output GEMM)
#pragma unroll
        for (int i = 0; i < 4; i++) {
#pragma unroll
            for (int jj = 0; jj < 4; jj++) {
                size_t row0 = (size_t)(rowBase + warpRow + i * 16 + er);
                size_t col = (size_t)(colBase + warpCol + jj * 8 + ec);
                float2 v0 = make_float2(acc[i][jj][0], acc[i][jj][1]);
                float2 v1 = make_float2(acc[i][jj][2], acc[i][jj][3]);
                *reinterpret_cast<float2*>(Cf + row0 * CC + col) = v0;
                *reinterpret_cast<float2*>(Cf + (row0 + 8) * CC + col) = v1;
            }
        }
    }
}

// ---------------------------------------------------------------------------
// WKV pass 1: per-(chunk, b, c) local stabilized sums (zero initial state)
// ---------------------------------------------------------------------------
__global__ void wkv_pass1(const float* __restrict__ k,
                          const __half* __restrict__ v,
                          const float* __restrict__ time_decay) {
    int idx = blockIdx.x * blockDim.x + threadIdx.x;
    if (idx >= NCHK * NBC) return;
    int c = idx % CC;
    int b = (idx / CC) % BB;
    int chunk = idx / NBC;

    const float w = -__expf(time_decay[c]);
    float s_v = 0.f, s_d = 0.f, m = -1e38f;
    size_t base = ((size_t)b * TT + chunk * LCHK) * CC + c;

#pragma unroll 4
    for (int t = 0; t < LCHK; t++) {
        size_t g = base + (size_t)t * CC;
        float kt = k[g];
        float vt = __half2float(v[g]);
        float mw = m + w;
        float mn = fmaxf(mw, kt);
        float e1 = __expf(mw - mn);
        float e2 = __expf(kt - mn);
        s_v = e1 * s_v + e2 * vt;
        s_d = e1 * s_d + e2;
        m = mn;
    }
    g_sv[idx] = s_v;
    g_sd[idx] = s_d;
    g_sm[idx] = m;
}

// ---------------------------------------------------------------------------
// WKV pass 2: sequential prefix over chunks per (b, c)
// ---------------------------------------------------------------------------
__global__ void wkv_pass2(const float* __restrict__ time_decay) {
    int idx = blockIdx.x * blockDim.x + threadIdx.x;
    if (idx >= NBC) return;
    int c = idx % CC;
    const float w = -__expf(time_decay[c]);
    const float Lw = (float)LCHK * w;

    float num = 0.f, den = 0.f, mx = -1e38f;
#pragma unroll
    for (int ch = 0; ch < NCHK; ch++) {
        size_t o = (size_t)ch * NBC + idx;
        g_inum[o] = num;
        g_iden[o] = den;
        g_imx[o] = mx;
        float ms = g_sm[o];
        float mo = mx + Lw;
        float mn = fmaxf(mo, ms);
        float e1 = __expf(mo - mn);
        float e2 = __expf(ms - mn);
        num = e1 * num + e2 * g_sv[o];
        den = e1 * den + e2 * g_sd[o];
        mx = mn;
    }
}

// ---------------------------------------------------------------------------
// WKV pass 3: replay reference step inside each chunk; fuse sigmoid(r), fp16
// ---------------------------------------------------------------------------
__global__ void wkv_pass3(const float* __restrict__ k,
                          const __half* __restrict__ v,
                          const __half* __restrict__ r,
                          const float* __restrict__ time_decay,
                          const float* __restrict__ time_first,
                          __half* __restrict__ s) {
    int idx = blockIdx.x * blockDim.x + threadIdx.x;
    if (idx >= NCHK * NBC) return;
    int c = idx % CC;
    int b = (idx / CC) % BB;
    int chunk = idx / NBC;

    const float w = -__expf(time_decay[c]);
    const float u = time_first[c];

    float num = g_inum[idx];
    float den = g_iden[idx];
    float mx  = g_imx[idx];
    size_t base = ((size_t)b * TT + chunk * LCHK) * CC + c;

#pragma unroll 2
    for (int t = 0; t < LCHK; t++) {
        size_t g = base + (size_t)t * CC;
        float kt = k[g];
        float vt = __half2float(v[g]);
        float rv = __half2float(r[g]);

        float ku = kt + u;
        float max_out = fmaxf(mx, ku);
        float e1 = __expf(mx - max_out);
        float e2 = __expf(ku - max_out);
        float o = __fdividef(e1 * num + e2 * vt, e1 * den + e2);

        float mw = mx + w;
        float max_st = fmaxf(mw, kt);
        float e1s = __expf(mw - max_st);
        float e2s = __expf(kt - max_st);
        num = e1s * num + e2s * vt;
        den = e1s * den + e2s;
        mx = max_st;

        float sr = __fdividef(1.f, 1.f + __expf(-rv));
        s[g] = __float2half_rn(sr * o);
    }
}

// ---------------------------------------------------------------------------
// Launch
// ---------------------------------------------------------------------------
extern "C" void kernel_launch(void* const* d_in, const int* in_sizes, int n_in,
                              void* d_out, int out_size) {
    const float* x   = (const float*)d_in[0];
    const float* td  = (const float*)d_in[1];
    const float* tf  = (const float*)d_in[2];
    const float* tmk = (const float*)d_in[3];
    const float* tmv = (const float*)d_in[4];
    const float* tmr = (const float*)d_in[5];
    const float* Wk  = (const float*)d_in[6];
    const float* Wv  = (const float*)d_in[7];
    const float* Wr  = (const float*)d_in[8];
    const float* Wo  = (const float*)d_in[9];
    float* out = (float*)d_out;

    static bool inited = false;
    static __half *p_xk, *p_xv, *p_xr, *p_w, *p_s, *p_v16, *p_r16;
    static float *p_k;
    if (!inited) {
        cudaGetSymbolAddress((void**)&p_xk, g_xk16);
        cudaGetSymbolAddress((void**)&p_xv, g_xv16);
        cudaGetSymbolAddress((void**)&p_xr, g_xr16);
        cudaGetSymbolAddress((void**)&p_w,  g_w16);
        cudaGetSymbolAddress((void**)&p_k,  g_k);
        cudaGetSymbolAddress((void**)&p_v16, g_v16);
        cudaGetSymbolAddress((void**)&p_r16, g_r16);
        cudaGetSymbolAddress((void**)&p_s,  g_s16);
        cudaFuncSetAttribute(gemm_f16,
                             cudaFuncAttributeMaxDynamicSharedMemorySize, GSMEM);
        inited = true;
    }

    // 1. convert the 4 weight matrices to fp16 (one launch)
    {
        int n = 4 * CC * CC / 4;
        cvt16_all<<<(n + 255) / 256, 256>>>((const float4*)Wk, (const float4*)Wv,
                                            (const float4*)Wr, (const float4*)Wo, p_w);
    }

    // 2. time-shift mixing + fp16 convert
    {
        int n4 = NELEM / 4;
        mix16_kernel<<<(n4 + 255) / 256, 256>>>(
            (const float4*)x, (const float4*)tmk, (const float4*)tmv, (const float4*)tmr);
    }

    // 3. fused projection GEMMs: z picks (xk,Wk,k fp32)/(xv,Wv,v fp16)/(xr,Wr,r fp16)
    {
        dim3 gg(CC / BN, MM / BM, 3);  // (16, 64, 3)
        gemm_f16<<<gg, 256, GSMEM>>>(p_xk, p_xv, p_xr, p_w, p_k, p_v16, p_r16, 1);
    }

    // 4. WKV chunked scan (3 passes) + sigmoid fusion (outputs fp16)
    {
        int n1 = NCHK * NBC;  // 524288
        wkv_pass1<<<(n1 + 255) / 256, 256>>>(p_k, p_v16, td);
        wkv_pass2<<<(NBC + 255) / 256, 256>>>(td);
        wkv_pass3<<<(n1 + 255) / 256, 256>>>(p_k, p_v16, p_r16, td, tf, p_s);
    }

    // 5. output GEMM into d_out (fp32 epilogue)
    {
        dim3 gg(CC / BN, MM / BM, 1);
        gemm_f16<<<gg, 256, GSMEM>>>(p_s, p_s, p_s, p_w + 3ULL * CC * CC,
                                     out, nullptr, nullptr, 0);
    }
}

// round 11
// speedup vs baseline: 4.4873x; 1.0075x over previous
#include <cuda_runtime.h>
#include <cuda_fp16.h>
#include <cstdint>

// Problem dims
#define BB 8
#define TT 1024
#define CC 2048
#define MM (BB * TT)          // 8192
#define NELEM (BB * TT * CC)  // 16,777,216

// WKV chunking
#define NCHK 32
#define LCHK (TT / NCHK)      // 32
#define NBC (BB * CC)         // 16384

// GEMM tiling (HMMA mma.sync, fp16, BK=64, 3-stage pipeline)
#define BM 128
#define BN 128
#define BKK 64
#define NITER (CC / BKK)      // 32
#define SROWB 144             // 64 fp16 = 128B + 16B pad
#define TILEB (128 * SROWB)   // 18432
#define STAGEB (2 * TILEB)    // 36864 (A + B)
#define NSTAGE 3
#define GSMEM (NSTAGE * STAGEB)  // 110592

#define MIXBLK ((NELEM / 4) / 256)   // 16384 blocks for mixing
#define CVTBLK ((CC * CC) / 256)     // 16384 blocks for weight cvt

// ---------------------------------------------------------------------------
// Scratch (static device globals; no allocation anywhere)
// ---------------------------------------------------------------------------
__device__ __half g_xk16[NELEM], g_xv16[NELEM], g_xr16[NELEM];
__device__ __half g_w16[4ULL * CC * CC];
__device__ __half g_k16[NELEM], g_v16[NELEM], g_r16[NELEM];
__device__ __half g_s16[NELEM];
// wkv chunk-scan scratch
__device__ float g_sv[NCHK * NBC], g_sd[NCHK * NBC], g_sm[NCHK * NBC];
__device__ float g_inum[NCHK * NBC], g_iden[NCHK * NBC], g_imx[NCHK * NBC];

// ---------------------------------------------------------------------------
// Helpers
// ---------------------------------------------------------------------------
__device__ __forceinline__ uint32_t smem_u32(const void* p) {
    uint32_t a;
    asm("{ .reg .u64 t; cvta.to.shared.u64 t, %1; cvt.u32.u64 %0, t; }"
        : "=r"(a) : "l"(p));
    return a;
}
__device__ __forceinline__ void cp_async16(uint32_t saddr, const void* gaddr) {
    asm volatile("cp.async.cg.shared.global [%0], [%1], 16;"
                 :: "r"(saddr), "l"(gaddr));
}
__device__ __forceinline__ void cp_commit() { asm volatile("cp.async.commit_group;"); }
__device__ __forceinline__ void cp_wait1() { asm volatile("cp.async.wait_group 1;"); }
__device__ __forceinline__ void cp_wait0() { asm volatile("cp.async.wait_group 0;"); }

__device__ __forceinline__ void ldsm_x4(uint32_t addr, uint32_t& r0, uint32_t& r1,
                                        uint32_t& r2, uint32_t& r3) {
    asm volatile("ldmatrix.sync.aligned.m8n8.x4.shared.b16 {%0,%1,%2,%3}, [%4];"
                 : "=r"(r0), "=r"(r1), "=r"(r2), "=r"(r3) : "r"(addr));
}
__device__ __forceinline__ void mma_f16(float* c, const uint32_t* a, const uint32_t* b) {
    asm volatile(
        "mma.sync.aligned.m16n8k16.row.col.f32.f16.f16.f32 "
        "{%0,%1,%2,%3}, {%4,%5,%6,%7}, {%8,%9}, {%0,%1,%2,%3};"
        : "+f"(c[0]), "+f"(c[1]), "+f"(c[2]), "+f"(c[3])
        : "r"(a[0]), "r"(a[1]), "r"(a[2]), "r"(a[3]), "r"(b[0]), "r"(b[1]));
}

__device__ __forceinline__ void store_h4(__half* __restrict__ dst, size_t base, float4 v) {
    __half2 a = __floats2half2_rn(v.x, v.y);
    __half2 b = __floats2half2_rn(v.z, v.w);
    *reinterpret_cast<__half2*>(dst + base)     = a;
    *reinterpret_cast<__half2*>(dst + base + 2) = b;
}

// ---------------------------------------------------------------------------
// Kernel: fused prep — blocks [0, MIXBLK) do time-shift mixing (+cvt),
// blocks [MIXBLK, MIXBLK+CVTBLK) convert the 4 weight matrices.
// ---------------------------------------------------------------------------
__global__ void prep_kernel(const float4* __restrict__ x4,
                            const float4* __restrict__ tmk4,
                            const float4* __restrict__ tmv4,
                            const float4* __restrict__ tmr4,
                            const float4* __restrict__ w0,
                            const float4* __restrict__ w1,
                            const float4* __restrict__ w2,
                            const float4* __restrict__ w3,
                            __half* __restrict__ wdst) {
    const int blk = blockIdx.x;
    if (blk < MIXBLK) {
        const int C4 = CC / 4;
        int i = blk * 256 + threadIdx.x;
        int c4 = i % C4;
        int t = (i / C4) % TT;

        float4 xc = x4[i];
        float4 xs = make_float4(0.f, 0.f, 0.f, 0.f);
        if (t > 0) xs = x4[i - C4];

        float4 mk = tmk4[c4], mv = tmv4[c4], mr = tmr4[c4];
        float4 ok, ov, orr;
        ok.x  = xc.x * mk.x + xs.x * (1.f - mk.x);
        ok.y  = xc.y * mk.y + xs.y * (1.f - mk.y);
        ok.z  = xc.z * mk.z + xs.z * (1.f - mk.z);
        ok.w  = xc.w * mk.w + xs.w * (1.f - mk.w);
        ov.x  = xc.x * mv.x + xs.x * (1.f - mv.x);
        ov.y  = xc.y * mv.y + xs.y * (1.f - mv.y);
        ov.z  = xc.z * mv.z + xs.z * (1.f - mv.z);
        ov.w  = xc.w * mv.w + xs.w * (1.f - mv.w);
        orr.x = xc.x * mr.x + xs.x * (1.f - mr.x);
        orr.y = xc.y * mr.y + xs.y * (1.f - mr.y);
        orr.z = xc.z * mr.z + xs.z * (1.f - mr.z);
        orr.w = xc.w * mr.w + xs.w * (1.f - mr.w);

        size_t base = (size_t)i * 4;
        store_h4(g_xk16, base, ok);
        store_h4(g_xv16, base, ov);
        store_h4(g_xr16, base, orr);
    } else {
        const int n4 = CC * CC / 4;
        int i = (blk - MIXBLK) * 256 + threadIdx.x;   // [0, 4*n4)
        int m = i / n4;
        int o = i - m * n4;
        const float4* src = (m == 0) ? w0 : (m == 1) ? w1 : (m == 2) ? w2 : w3;
        store_h4(wdst, (size_t)i * 4, src[o]);
    }
}

// ---------------------------------------------------------------------------
// Kernel: fp16 HMMA GEMM, BK=64, 3-stage cp.async pipeline, one sync/iter.
// proj=1: gridDim.z selects (A,B,Ch); all outputs fp16.
// proj=0: fp32 output (the final Wo GEMM into d_out).
// ---------------------------------------------------------------------------
__global__ __launch_bounds__(256, 2)
void gemm_f16(const __half* __restrict__ A0, const __half* __restrict__ A1,
              const __half* __restrict__ A2, const __half* __restrict__ Bbase,
              float* __restrict__ Cf, __half* __restrict__ Ch0,
              __half* __restrict__ Ch1, __half* __restrict__ Ch2, int proj) {
    extern __shared__ __align__(128) char smem[];
    const uint32_t sb = smem_u32(smem);
    const int z = blockIdx.z;
    const __half* A = (z == 0) ? A0 : (z == 1) ? A1 : A2;
    const __half* B = Bbase + (size_t)z * CC * CC;

    const int tid = threadIdx.x;
    const int wid = tid >> 5;
    const int lane = tid & 31;
    const int wm = wid >> 2;
    const int wn = wid & 3;
    const int rowBase = blockIdx.y * BM;
    const int colBase = blockIdx.x * BN;
    const int warpRow = wm * 64;
    const int warpCol = wn * 32;

    const uint32_t OF_A = 0, OF_B = TILEB;

    auto issue_stage = [&](int buf, int k0) {
        uint32_t sbase = sb + buf * STAGEB;
#pragma unroll
        for (int it = 0; it < 4; it++) {
            int idx = tid + it * 256;
            int r = idx >> 3, c = idx & 7;
            uint32_t so = (uint32_t)(r * SROWB + c * 16);
            size_t gA = (size_t)(rowBase + r) * CC + k0 + c * 8;
            size_t gB = (size_t)(colBase + r) * CC + k0 + c * 8;
            cp_async16(sbase + OF_A + so, A + gA);
            cp_async16(sbase + OF_B + so, B + gB);
        }
        cp_commit();
    };

    float acc[4][4][4];
#pragma unroll
    for (int i = 0; i < 4; i++)
#pragma unroll
        for (int j = 0; j < 4; j++)
#pragma unroll
            for (int q = 0; q < 4; q++) acc[i][j][q] = 0.f;

    const uint32_t aLaneOff =
        (uint32_t)((warpRow + (lane & 15)) * SROWB + (lane >> 4) * 16);
    const int bg = lane >> 3, bw = lane & 7;
    const uint32_t bLaneOff =
        (uint32_t)((warpCol + (bg >> 1) * 8 + bw) * SROWB + (bg & 1) * 16);

    issue_stage(0, 0);
    issue_stage(1, BKK);

    int buf = 0, nbuf = 2;
#pragma unroll 1
    for (int j = 0; j < NITER; j++) {
        if (j + 2 < NITER) cp_wait1(); else cp_wait0();
        __syncthreads();
        if (j + 2 < NITER) issue_stage(nbuf, (j + 2) * BKK);

        const uint32_t sbase = sb + buf * STAGEB;
#pragma unroll
        for (int kk = 0; kk < 4; kk++) {
            const uint32_t kOff = kk * 32;
            uint32_t ah[4][4], bx[4][2];
#pragma unroll
            for (int i = 0; i < 4; i++) {
                uint32_t ad = sbase + OF_A + aLaneOff + i * 16 * SROWB + kOff;
                ldsm_x4(ad, ah[i][0], ah[i][1], ah[i][2], ah[i][3]);
            }
#pragma unroll
            for (int jp = 0; jp < 2; jp++) {
                uint32_t bd = sbase + OF_B + bLaneOff + jp * 16 * SROWB + kOff;
                ldsm_x4(bd, bx[jp * 2][0], bx[jp * 2][1],
                        bx[jp * 2 + 1][0], bx[jp * 2 + 1][1]);
            }
#pragma unroll
            for (int i = 0; i < 4; i++)
#pragma unroll
                for (int jj = 0; jj < 4; jj++) mma_f16(acc[i][jj], ah[i], bx[jj]);
        }
        buf = (buf == NSTAGE - 1) ? 0 : buf + 1;
        nbuf = (nbuf == NSTAGE - 1) ? 0 : nbuf + 1;
    }

    const int er = lane >> 2, ec = (lane & 3) * 2;
    if (proj) {
        __half* Ch = (z == 0) ? Ch0 : (z == 1) ? Ch1 : Ch2;
#pragma unroll
        for (int i = 0; i < 4; i++) {
#pragma unroll
            for (int jj = 0; jj < 4; jj++) {
                size_t row0 = (size_t)(rowBase + warpRow + i * 16 + er);
                size_t col = (size_t)(colBase + warpCol + jj * 8 + ec);
                __half2 v0 = __floats2half2_rn(acc[i][jj][0], acc[i][jj][1]);
                __half2 v1 = __floats2half2_rn(acc[i][jj][2], acc[i][jj][3]);
                *reinterpret_cast<__half2*>(Ch + row0 * CC + col) = v0;
                *reinterpret_cast<__half2*>(Ch + (row0 + 8) * CC + col) = v1;
            }
        }
    } else {
#pragma unroll
        for (int i = 0; i < 4; i++) {
#pragma unroll
            for (int jj = 0; jj < 4; jj++) {
                size_t row0 = (size_t)(rowBase + warpRow + i * 16 + er);
                size_t col = (size_t)(colBase + warpCol + jj * 8 + ec);
                float2 v0 = make_float2(acc[i][jj][0], acc[i][jj][1]);
                float2 v1 = make_float2(acc[i][jj][2], acc[i][jj][3]);
                *reinterpret_cast<float2*>(Cf + row0 * CC + col) = v0;
                *reinterpret_cast<float2*>(Cf + (row0 + 8) * CC + col) = v1;
            }
        }
    }
}

// ---------------------------------------------------------------------------
// WKV pass 1: two channels per thread (half2), local stabilized sums
// ---------------------------------------------------------------------------
__global__ void wkv_pass1(const __half* __restrict__ k,
                          const __half* __restrict__ v,
                          const float* __restrict__ time_decay) {
    int idx = blockIdx.x * blockDim.x + threadIdx.x;   // over NCHK*NBC/2
    if (idx >= NCHK * NBC / 2) return;
    int c2 = idx % (CC / 2);
    int c = c2 * 2;
    int b = (idx / (CC / 2)) % BB;
    int chunk = idx / (NBC / 2);

    const float w0 = -__expf(time_decay[c]);
    const float w1 = -__expf(time_decay[c + 1]);
    float sv0 = 0.f, sd0 = 0.f, m0 = -1e38f;
    float sv1 = 0.f, sd1 = 0.f, m1 = -1e38f;
    size_t base = ((size_t)b * TT + chunk * LCHK) * CC + c;

#pragma unroll 4
    for (int t = 0; t < LCHK; t++) {
        size_t g = base + (size_t)t * CC;
        __half2 kh = *reinterpret_cast<const __half2*>(k + g);
        __half2 vh = *reinterpret_cast<const __half2*>(v + g);
        float k0 = __half2float(kh.x), k1 = __half2float(kh.y);
        float v0 = __half2float(vh.x), v1 = __half2float(vh.y);

        float mw0 = m0 + w0, mw1 = m1 + w1;
        float mn0 = fmaxf(mw0, k0), mn1 = fmaxf(mw1, k1);
        float e10 = __expf(mw0 - mn0), e11 = __expf(mw1 - mn1);
        float e20 = __expf(k0 - mn0), e21 = __expf(k1 - mn1);
        sv0 = e10 * sv0 + e20 * v0;  sv1 = e11 * sv1 + e21 * v1;
        sd0 = e10 * sd0 + e20;       sd1 = e11 * sd1 + e21;
        m0 = mn0;                    m1 = mn1;
    }
    size_t o = (size_t)chunk * NBC + (size_t)b * CC + c;
    g_sv[o] = sv0; g_sv[o + 1] = sv1;
    g_sd[o] = sd0; g_sd[o + 1] = sd1;
    g_sm[o] = m0;  g_sm[o + 1] = m1;
}

// ---------------------------------------------------------------------------
// WKV pass 2: sequential prefix over chunks per (b, c)
// ---------------------------------------------------------------------------
__global__ void wkv_pass2(const float* __restrict__ time_decay) {
    int idx = blockIdx.x * blockDim.x + threadIdx.x;
    if (idx >= NBC) return;
    int c = idx % CC;
    const float w = -__expf(time_decay[c]);
    const float Lw = (float)LCHK * w;

    float num = 0.f, den = 0.f, mx = -1e38f;
#pragma unroll
    for (int ch = 0; ch < NCHK; ch++) {
        size_t o = (size_t)ch * NBC + idx;
        g_inum[o] = num;
        g_iden[o] = den;
        g_imx[o] = mx;
        float ms = g_sm[o];
        float mo = mx + Lw;
        float mn = fmaxf(mo, ms);
        float e1 = __expf(mo - mn);
        float e2 = __expf(ms - mn);
        num = e1 * num + e2 * g_sv[o];
        den = e1 * den + e2 * g_sd[o];
        mx = mn;
    }
}

// ---------------------------------------------------------------------------
// WKV pass 3: two channels per thread; replay reference step; sigmoid fusion
// ---------------------------------------------------------------------------
__global__ void wkv_pass3(const __half* __restrict__ k,
                          const __half* __restrict__ v,
                          const __half* __restrict__ r,
                          const float* __restrict__ time_decay,
                          const float* __restrict__ time_first,
                          __half* __restrict__ s) {
    int idx = blockIdx.x * blockDim.x + threadIdx.x;   // over NCHK*NBC/2
    if (idx >= NCHK * NBC / 2) return;
    int c2 = idx % (CC / 2);
    int c = c2 * 2;
    int b = (idx / (CC / 2)) % BB;
    int chunk = idx / (NBC / 2);

    const float w0 = -__expf(time_decay[c]);
    const float w1 = -__expf(time_decay[c + 1]);
    const float u0 = time_first[c];
    const float u1 = time_first[c + 1];

    size_t o = (size_t)chunk * NBC + (size_t)b * CC + c;
    float num0 = g_inum[o], num1 = g_inum[o + 1];
    float den0 = g_iden[o], den1 = g_iden[o + 1];
    float mx0 = g_imx[o],   mx1 = g_imx[o + 1];
    size_t base = ((size_t)b * TT + chunk * LCHK) * CC + c;

#pragma unroll 2
    for (int t = 0; t < LCHK; t++) {
        size_t g = base + (size_t)t * CC;
        __half2 kh = *reinterpret_cast<const __half2*>(k + g);
        __half2 vh = *reinterpret_cast<const __half2*>(v + g);
        __half2 rh = *reinterpret_cast<const __half2*>(r + g);
        float k0 = __half2float(kh.x), k1 = __half2float(kh.y);
        float v0 = __half2float(vh.x), v1 = __half2float(vh.y);
        float r0 = __half2float(rh.x), r1 = __half2float(rh.y);

        float ku0 = k0 + u0, ku1 = k1 + u1;
        float mo0 = fmaxf(mx0, ku0), mo1 = fmaxf(mx1, ku1);
        float a10 = __expf(mx0 - mo0), a11 = __expf(mx1 - mo1);
        float a20 = __expf(ku0 - mo0), a21 = __expf(ku1 - mo1);
        float out0 = __fdividef(a10 * num0 + a20 * v0, a10 * den0 + a20);
        float out1 = __fdividef(a11 * num1 + a21 * v1, a11 * den1 + a21);

        float mw0 = mx0 + w0, mw1 = mx1 + w1;
        float ms0 = fmaxf(mw0, k0), ms1 = fmaxf(mw1, k1);
        float b10 = __expf(mw0 - ms0), b11 = __expf(mw1 - ms1);
        float b20 = __expf(k0 - ms0), b21 = __expf(k1 - ms1);
        num0 = b10 * num0 + b20 * v0;  num1 = b11 * num1 + b21 * v1;
        den0 = b10 * den0 + b20;       den1 = b11 * den1 + b21;
        mx0 = ms0;                     mx1 = ms1;

        float sr0 = __fdividef(1.f, 1.f + __expf(-r0));
        float sr1 = __fdividef(1.f, 1.f + __expf(-r1));
        __half2 sh = __floats2half2_rn(sr0 * out0, sr1 * out1);
        *reinterpret_cast<__half2*>(s + g) = sh;
    }
}

// ---------------------------------------------------------------------------
// Launch
// ---------------------------------------------------------------------------
extern "C" void kernel_launch(void* const* d_in, const int* in_sizes, int n_in,
                              void* d_out, int out_size) {
    const float* x   = (const float*)d_in[0];
    const float* td  = (const float*)d_in[1];
    const float* tf  = (const float*)d_in[2];
    const float* tmk = (const float*)d_in[3];
    const float* tmv = (const float*)d_in[4];
    const float* tmr = (const float*)d_in[5];
    const float* Wk  = (const float*)d_in[6];
    const float* Wv  = (const float*)d_in[7];
    const float* Wr  = (const float*)d_in[8];
    const float* Wo  = (const float*)d_in[9];
    float* out = (float*)d_out;

    static bool inited = false;
    static __half *p_xk, *p_xv, *p_xr, *p_w, *p_s, *p_k16, *p_v16, *p_r16;
    if (!inited) {
        cudaGetSymbolAddress((void**)&p_xk, g_xk16);
        cudaGetSymbolAddress((void**)&p_xv, g_xv16);
        cudaGetSymbolAddress((void**)&p_xr, g_xr16);
        cudaGetSymbolAddress((void**)&p_w,  g_w16);
        cudaGetSymbolAddress((void**)&p_k16, g_k16);
        cudaGetSymbolAddress((void**)&p_v16, g_v16);
        cudaGetSymbolAddress((void**)&p_r16, g_r16);
        cudaGetSymbolAddress((void**)&p_s,  g_s16);
        cudaFuncSetAttribute(gemm_f16,
                             cudaFuncAttributeMaxDynamicSharedMemorySize, GSMEM);
        inited = true;
    }

    // 1. fused prep: mixing + weight conversion in one launch
    prep_kernel<<<MIXBLK + CVTBLK, 256>>>(
        (const float4*)x, (const float4*)tmk, (const float4*)tmv, (const float4*)tmr,
        (const float4*)Wk, (const float4*)Wv, (const float4*)Wr, (const float4*)Wo,
        p_w);

    // 2. fused projection GEMMs (all fp16 outputs)
    {
        dim3 gg(CC / BN, MM / BM, 3);  // (16, 64, 3)
        gemm_f16<<<gg, 256, GSMEM>>>(p_xk, p_xv, p_xr, p_w,
                                     nullptr, p_k16, p_v16, p_r16, 1);
    }

    // 3. WKV chunked scan (3 passes) + sigmoid fusion
    {
        int n1 = NCHK * NBC / 2;  // 262144
        wkv_pass1<<<(n1 + 255) / 256, 256>>>(p_k16, p_v16, td);
        wkv_pass2<<<(NBC + 255) / 256, 256>>>(td);
        wkv_pass3<<<(n1 + 255) / 256, 256>>>(p_k16, p_v16, p_r16, td, tf, p_s);
    }

    // 4. output GEMM into d_out (fp32 epilogue)
    {
        dim3 gg(CC / BN, MM / BM, 1);
        gemm_f16<<<gg, 256, GSMEM>>>(p_s, p_s, p_s, p_w + 3ULL * CC * CC,
                                     out, nullptr, nullptr, nullptr, 0);
    }
}

// round 12
// speedup vs baseline: 4.5389x; 1.0115x over previous
#include <cuda_runtime.h>
#include <cuda_fp16.h>
#include <cstdint>

// Problem dims
#define BB 8
#define TT 1024
#define CC 2048
#define MM (BB * TT)          // 8192
#define NELEM (BB * TT * CC)  // 16,777,216

// WKV chunking
#define NCHK 32
#define LCHK (TT / NCHK)      // 32
#define WCHAN 32              // channels per wkv block
#define WTHR (NCHK * WCHAN / 2)  // 512 threads

// GEMM tiling (HMMA mma.sync, fp16, BK=64, 3-stage pipeline)
#define BM 128
#define BN 128
#define BKK 64
#define NITER (CC / BKK)      // 32
#define SROWB 144             // 64 fp16 = 128B + 16B pad
#define TILEB (128 * SROWB)   // 18432
#define STAGEB (2 * TILEB)    // 36864 (A + B)
#define NSTAGE 3
#define GSMEM (NSTAGE * STAGEB)  // 110592

#define MIXBLK ((NELEM / 4) / 256)   // 16384 blocks for mixing
#define CVTBLK ((CC * CC) / 256)     // 16384 blocks for weight cvt

// ---------------------------------------------------------------------------
// Scratch (static device globals; no allocation anywhere)
// ---------------------------------------------------------------------------
__device__ __half g_xk16[NELEM], g_xv16[NELEM], g_xr16[NELEM];
__device__ __half g_w16[4ULL * CC * CC];
__device__ __half g_k16[NELEM], g_v16[NELEM], g_r16[NELEM];
__device__ __half g_s16[NELEM];

// ---------------------------------------------------------------------------
// Helpers
// ---------------------------------------------------------------------------
__device__ __forceinline__ uint32_t smem_u32(const void* p) {
    uint32_t a;
    asm("{ .reg .u64 t; cvta.to.shared.u64 t, %1; cvt.u32.u64 %0, t; }"
        : "=r"(a) : "l"(p));
    return a;
}
__device__ __forceinline__ void cp_async16(uint32_t saddr, const void* gaddr) {
    asm volatile("cp.async.cg.shared.global [%0], [%1], 16;"
                 :: "r"(saddr), "l"(gaddr));
}
__device__ __forceinline__ void cp_commit() { asm volatile("cp.async.commit_group;"); }
__device__ __forceinline__ void cp_wait1() { asm volatile("cp.async.wait_group 1;"); }
__device__ __forceinline__ void cp_wait0() { asm volatile("cp.async.wait_group 0;"); }

__device__ __forceinline__ void ldsm_x4(uint32_t addr, uint32_t& r0, uint32_t& r1,
                                        uint32_t& r2, uint32_t& r3) {
    asm volatile("ldmatrix.sync.aligned.m8n8.x4.shared.b16 {%0,%1,%2,%3}, [%4];"
                 : "=r"(r0), "=r"(r1), "=r"(r2), "=r"(r3) : "r"(addr));
}
__device__ __forceinline__ void mma_f16(float* c, const uint32_t* a, const uint32_t* b) {
    asm volatile(
        "mma.sync.aligned.m16n8k16.row.col.f32.f16.f16.f32 "
        "{%0,%1,%2,%3}, {%4,%5,%6,%7}, {%8,%9}, {%0,%1,%2,%3};"
        : "+f"(c[0]), "+f"(c[1]), "+f"(c[2]), "+f"(c[3])
        : "r"(a[0]), "r"(a[1]), "r"(a[2]), "r"(a[3]), "r"(b[0]), "r"(b[1]));
}

__device__ __forceinline__ void store_h4(__half* __restrict__ dst, size_t base, float4 v) {
    __half2 a = __floats2half2_rn(v.x, v.y);
    __half2 b = __floats2half2_rn(v.z, v.w);
    *reinterpret_cast<__half2*>(dst + base)     = a;
    *reinterpret_cast<__half2*>(dst + base + 2) = b;
}

// ---------------------------------------------------------------------------
// Kernel: fused prep — blocks [0, MIXBLK) do time-shift mixing (+cvt),
// blocks [MIXBLK, MIXBLK+CVTBLK) convert the 4 weight matrices.
// ---------------------------------------------------------------------------
__global__ void prep_kernel(const float4* __restrict__ x4,
                            const float4* __restrict__ tmk4,
                            const float4* __restrict__ tmv4,
                            const float4* __restrict__ tmr4,
                            const float4* __restrict__ w0,
                            const float4* __restrict__ w1,
                            const float4* __restrict__ w2,
                            const float4* __restrict__ w3,
                            __half* __restrict__ wdst) {
    const int blk = blockIdx.x;
    if (blk < MIXBLK) {
        const int C4 = CC / 4;
        int i = blk * 256 + threadIdx.x;
        int c4 = i % C4;
        int t = (i / C4) % TT;

        float4 xc = x4[i];
        float4 xs = make_float4(0.f, 0.f, 0.f, 0.f);
        if (t > 0) xs = x4[i - C4];

        float4 mk = tmk4[c4], mv = tmv4[c4], mr = tmr4[c4];
        float4 ok, ov, orr;
        ok.x  = xc.x * mk.x + xs.x * (1.f - mk.x);
        ok.y  = xc.y * mk.y + xs.y * (1.f - mk.y);
        ok.z  = xc.z * mk.z + xs.z * (1.f - mk.z);
        ok.w  = xc.w * mk.w + xs.w * (1.f - mk.w);
        ov.x  = xc.x * mv.x + xs.x * (1.f - mv.x);
        ov.y  = xc.y * mv.y + xs.y * (1.f - mv.y);
        ov.z  = xc.z * mv.z + xs.z * (1.f - mv.z);
        ov.w  = xc.w * mv.w + xs.w * (1.f - mv.w);
        orr.x = xc.x * mr.x + xs.x * (1.f - mr.x);
        orr.y = xc.y * mr.y + xs.y * (1.f - mr.y);
        orr.z = xc.z * mr.z + xs.z * (1.f - mr.z);
        orr.w = xc.w * mr.w + xs.w * (1.f - mr.w);

        size_t base = (size_t)i * 4;
        store_h4(g_xk16, base, ok);
        store_h4(g_xv16, base, ov);
        store_h4(g_xr16, base, orr);
    } else {
        const int n4 = CC * CC / 4;
        int i = (blk - MIXBLK) * 256 + threadIdx.x;   // [0, 4*n4)
        int m = i / n4;
        int o = i - m * n4;
        const float4* src = (m == 0) ? w0 : (m == 1) ? w1 : (m == 2) ? w2 : w3;
        store_h4(wdst, (size_t)i * 4, src[o]);
    }
}

// ---------------------------------------------------------------------------
// Kernel: fp16 HMMA GEMM, BK=64, 3-stage cp.async pipeline, one sync/iter.
// proj=1: gridDim.z selects (A,B,Ch); all outputs fp16.
// proj=0: fp32 output (the final Wo GEMM into d_out).
// ---------------------------------------------------------------------------
__global__ __launch_bounds__(256, 2)
void gemm_f16(const __half* __restrict__ A0, const __half* __restrict__ A1,
              const __half* __restrict__ A2, const __half* __restrict__ Bbase,
              float* __restrict__ Cf, __half* __restrict__ Ch0,
              __half* __restrict__ Ch1, __half* __restrict__ Ch2, int proj) {
    extern __shared__ __align__(128) char smem[];
    const uint32_t sb = smem_u32(smem);
    const int z = blockIdx.z;
    const __half* A = (z == 0) ? A0 : (z == 1) ? A1 : A2;
    const __half* B = Bbase + (size_t)z * CC * CC;

    const int tid = threadIdx.x;
    const int wid = tid >> 5;
    const int lane = tid & 31;
    const int wm = wid >> 2;
    const int wn = wid & 3;
    const int rowBase = blockIdx.y * BM;
    const int colBase = blockIdx.x * BN;
    const int warpRow = wm * 64;
    const int warpCol = wn * 32;

    const uint32_t OF_A = 0, OF_B = TILEB;

    auto issue_stage = [&](int buf, int k0) {
        uint32_t sbase = sb + buf * STAGEB;
#pragma unroll
        for (int it = 0; it < 4; it++) {
            int idx = tid + it * 256;
            int r = idx >> 3, c = idx & 7;
            uint32_t so = (uint32_t)(r * SROWB + c * 16);
            size_t gA = (size_t)(rowBase + r) * CC + k0 + c * 8;
            size_t gB = (size_t)(colBase + r) * CC + k0 + c * 8;
            cp_async16(sbase + OF_A + so, A + gA);
            cp_async16(sbase + OF_B + so, B + gB);
        }
        cp_commit();
    };

    float acc[4][4][4];
#pragma unroll
    for (int i = 0; i < 4; i++)
#pragma unroll
        for (int j = 0; j < 4; j++)
#pragma unroll
            for (int q = 0; q < 4; q++) acc[i][j][q] = 0.f;

    const uint32_t aLaneOff =
        (uint32_t)((warpRow + (lane & 15)) * SROWB + (lane >> 4) * 16);
    const int bg = lane >> 3, bw = lane & 7;
    const uint32_t bLaneOff =
        (uint32_t)((warpCol + (bg >> 1) * 8 + bw) * SROWB + (bg & 1) * 16);

    issue_stage(0, 0);
    issue_stage(1, BKK);

    int buf = 0, nbuf = 2;
#pragma unroll 1
    for (int j = 0; j < NITER; j++) {
        if (j + 2 < NITER) cp_wait1(); else cp_wait0();
        __syncthreads();
        if (j + 2 < NITER) issue_stage(nbuf, (j + 2) * BKK);

        const uint32_t sbase = sb + buf * STAGEB;
#pragma unroll
        for (int kk = 0; kk < 4; kk++) {
            const uint32_t kOff = kk * 32;
            uint32_t ah[4][4], bx[4][2];
#pragma unroll
            for (int i = 0; i < 4; i++) {
                uint32_t ad = sbase + OF_A + aLaneOff + i * 16 * SROWB + kOff;
                ldsm_x4(ad, ah[i][0], ah[i][1], ah[i][2], ah[i][3]);
            }
#pragma unroll
            for (int jp = 0; jp < 2; jp++) {
                uint32_t bd = sbase + OF_B + bLaneOff + jp * 16 * SROWB + kOff;
                ldsm_x4(bd, bx[jp * 2][0], bx[jp * 2][1],
                        bx[jp * 2 + 1][0], bx[jp * 2 + 1][1]);
            }
#pragma unroll
            for (int i = 0; i < 4; i++)
#pragma unroll
                for (int jj = 0; jj < 4; jj++) mma_f16(acc[i][jj], ah[i], bx[jj]);
        }
        buf = (buf == NSTAGE - 1) ? 0 : buf + 1;
        nbuf = (nbuf == NSTAGE - 1) ? 0 : nbuf + 1;
    }

    const int er = lane >> 2, ec = (lane & 3) * 2;
    if (proj) {
        __half* Ch = (z == 0) ? Ch0 : (z == 1) ? Ch1 : Ch2;
#pragma unroll
        for (int i = 0; i < 4; i++) {
#pragma unroll
            for (int jj = 0; jj < 4; jj++) {
                size_t row0 = (size_t)(rowBase + warpRow + i * 16 + er);
                size_t col = (size_t)(colBase + warpCol + jj * 8 + ec);
                __half2 v0 = __floats2half2_rn(acc[i][jj][0], acc[i][jj][1]);
                __half2 v1 = __floats2half2_rn(acc[i][jj][2], acc[i][jj][3]);
                *reinterpret_cast<__half2*>(Ch + row0 * CC + col) = v0;
                *reinterpret_cast<__half2*>(Ch + (row0 + 8) * CC + col) = v1;
            }
        }
    } else {
#pragma unroll
        for (int i = 0; i < 4; i++) {
#pragma unroll
            for (int jj = 0; jj < 4; jj++) {
                size_t row0 = (size_t)(rowBase + warpRow + i * 16 + er);
                size_t col = (size_t)(colBase + warpCol + jj * 8 + ec);
                float2 v0 = make_float2(acc[i][jj][0], acc[i][jj][1]);
                float2 v1 = make_float2(acc[i][jj][2], acc[i][jj][3]);
                *reinterpret_cast<float2*>(Cf + row0 * CC + col) = v0;
                *reinterpret_cast<float2*>(Cf + (row0 + 8) * CC + col) = v1;
            }
        }
    }
}

// ---------------------------------------------------------------------------
// Kernel: fused WKV — all 3 phases in one block per (batch, 32 channels).
// 512 threads = 32 chunks x 16 half2 channel-pairs.
// Phase 1: chunk-local stabilized sums -> smem.
// Phase 2: 32-thread in-place prefix over chunks (smem slots become incoming).
// Phase 3: replay reference step per chunk from smem incoming state.
// ---------------------------------------------------------------------------
__global__ __launch_bounds__(WTHR)
void wkv_fused(const __half* __restrict__ k,
               const __half* __restrict__ v,
               const __half* __restrict__ r,
               const float* __restrict__ time_decay,
               const float* __restrict__ time_first,
               __half* __restrict__ s) {
    __shared__ float s_v[NCHK][WCHAN];
    __shared__ float s_d[NCHK][WCHAN];
    __shared__ float s_m[NCHK][WCHAN];

    const int b = blockIdx.x / (CC / WCHAN);
    const int cbase = (blockIdx.x % (CC / WCHAN)) * WCHAN;
    const int tid = threadIdx.x;
    const int chunk = tid >> 4;       // 0..31
    const int cp = tid & 15;          // 0..15
    const int c = cbase + cp * 2;

    const float w0 = -__expf(time_decay[c]);
    const float w1 = -__expf(time_decay[c + 1]);
    const float u0 = time_first[c];
    const float u1 = time_first[c + 1];

    const size_t base = ((size_t)b * TT + chunk * LCHK) * CC + c;

    // Phase 1: local sums (zero initial state)
    {
        float sv0 = 0.f, sd0 = 0.f, m0 = -1e38f;
        float sv1 = 0.f, sd1 = 0.f, m1 = -1e38f;
#pragma unroll 4
        for (int t = 0; t < LCHK; t++) {
            size_t g = base + (size_t)t * CC;
            __half2 kh = *reinterpret_cast<const __half2*>(k + g);
            __half2 vh = *reinterpret_cast<const __half2*>(v + g);
            float k0 = __half2float(kh.x), k1 = __half2float(kh.y);
            float v0 = __half2float(vh.x), v1 = __half2float(vh.y);

            float mw0 = m0 + w0, mw1 = m1 + w1;
            float mn0 = fmaxf(mw0, k0), mn1 = fmaxf(mw1, k1);
            float e10 = __expf(mw0 - mn0), e11 = __expf(mw1 - mn1);
            float e20 = __expf(k0 - mn0), e21 = __expf(k1 - mn1);
            sv0 = e10 * sv0 + e20 * v0;  sv1 = e11 * sv1 + e21 * v1;
            sd0 = e10 * sd0 + e20;       sd1 = e11 * sd1 + e21;
            m0 = mn0;                    m1 = mn1;
        }
        s_v[chunk][cp * 2] = sv0;  s_v[chunk][cp * 2 + 1] = sv1;
        s_d[chunk][cp * 2] = sd0;  s_d[chunk][cp * 2 + 1] = sd1;
        s_m[chunk][cp * 2] = m0;   s_m[chunk][cp * 2 + 1] = m1;
    }
    __syncthreads();

    // Phase 2: in-place prefix over chunks; 32 threads, one channel each.
    if (tid < WCHAN) {
        const float w = -__expf(time_decay[cbase + tid]);
        const float Lw = (float)LCHK * w;
        float num = 0.f, den = 0.f, mx = -1e38f;
#pragma unroll
        for (int ch = 0; ch < NCHK; ch++) {
            float svv = s_v[ch][tid];
            float sdd = s_d[ch][tid];
            float smm = s_m[ch][tid];
            s_v[ch][tid] = num;
            s_d[ch][tid] = den;
            s_m[ch][tid] = mx;
            float mo = mx + Lw;
            float mn = fmaxf(mo, smm);
            float e1 = __expf(mo - mn);
            float e2 = __expf(smm - mn);
            num = e1 * num + e2 * svv;
            den = e1 * den + e2 * sdd;
            mx = mn;
        }
    }
    __syncthreads();

    // Phase 3: replay from incoming state; fuse sigmoid(r); emit fp16
    {
        float num0 = s_v[chunk][cp * 2], num1 = s_v[chunk][cp * 2 + 1];
        float den0 = s_d[chunk][cp * 2], den1 = s_d[chunk][cp * 2 + 1];
        float mx0  = s_m[chunk][cp * 2], mx1  = s_m[chunk][cp * 2 + 1];

#pragma unroll 2
        for (int t = 0; t < LCHK; t++) {
            size_t g = base + (size_t)t * CC;
            __half2 kh = *reinterpret_cast<const __half2*>(k + g);
            __half2 vh = *reinterpret_cast<const __half2*>(v + g);
            __half2 rh = *reinterpret_cast<const __half2*>(r + g);
            float k0 = __half2float(kh.x), k1 = __half2float(kh.y);
            float v0 = __half2float(vh.x), v1 = __half2float(vh.y);
            float r0 = __half2float(rh.x), r1 = __half2float(rh.y);

            float ku0 = k0 + u0, ku1 = k1 + u1;
            float mo0 = fmaxf(mx0, ku0), mo1 = fmaxf(mx1, ku1);
            float a10 = __expf(mx0 - mo0), a11 = __expf(mx1 - mo1);
            float a20 = __expf(ku0 - mo0), a21 = __expf(ku1 - mo1);
            float out0 = __fdividef(a10 * num0 + a20 * v0, a10 * den0 + a20);
            float out1 = __fdividef(a11 * num1 + a21 * v1, a11 * den1 + a21);

            float mw0 = mx0 + w0, mw1 = mx1 + w1;
            float ms0 = fmaxf(mw0, k0), ms1 = fmaxf(mw1, k1);
            float b10 = __expf(mw0 - ms0), b11 = __expf(mw1 - ms1);
            float b20 = __expf(k0 - ms0), b21 = __expf(k1 - ms1);
            num0 = b10 * num0 + b20 * v0;  num1 = b11 * num1 + b21 * v1;
            den0 = b10 * den0 + b20;       den1 = b11 * den1 + b21;
            mx0 = ms0;                     mx1 = ms1;

            float sr0 = __fdividef(1.f, 1.f + __expf(-r0));
            float sr1 = __fdividef(1.f, 1.f + __expf(-r1));
            __half2 sh = __floats2half2_rn(sr0 * out0, sr1 * out1);
            *reinterpret_cast<__half2*>(s + g) = sh;
        }
    }
}

// ---------------------------------------------------------------------------
// Launch
// ---------------------------------------------------------------------------
extern "C" void kernel_launch(void* const* d_in, const int* in_sizes, int n_in,
                              void* d_out, int out_size) {
    const float* x   = (const float*)d_in[0];
    const float* td  = (const float*)d_in[1];
    const float* tf  = (const float*)d_in[2];
    const float* tmk = (const float*)d_in[3];
    const float* tmv = (const float*)d_in[4];
    const float* tmr = (const float*)d_in[5];
    const float* Wk  = (const float*)d_in[6];
    const float* Wv  = (const float*)d_in[7];
    const float* Wr  = (const float*)d_in[8];
    const float* Wo  = (const float*)d_in[9];
    float* out = (float*)d_out;

    static bool inited = false;
    static __half *p_xk, *p_xv, *p_xr, *p_w, *p_s, *p_k16, *p_v16, *p_r16;
    if (!inited) {
        cudaGetSymbolAddress((void**)&p_xk, g_xk16);
        cudaGetSymbolAddress((void**)&p_xv, g_xv16);
        cudaGetSymbolAddress((void**)&p_xr, g_xr16);
        cudaGetSymbolAddress((void**)&p_w,  g_w16);
        cudaGetSymbolAddress((void**)&p_k16, g_k16);
        cudaGetSymbolAddress((void**)&p_v16, g_v16);
        cudaGetSymbolAddress((void**)&p_r16, g_r16);
        cudaGetSymbolAddress((void**)&p_s,  g_s16);
        cudaFuncSetAttribute(gemm_f16,
                             cudaFuncAttributeMaxDynamicSharedMemorySize, GSMEM);
        inited = true;
    }

    // 1. fused prep: mixing + weight conversion in one launch
    prep_kernel<<<MIXBLK + CVTBLK, 256>>>(
        (const float4*)x, (const float4*)tmk, (const float4*)tmv, (const float4*)tmr,
        (const float4*)Wk, (const float4*)Wv, (const float4*)Wr, (const float4*)Wo,
        p_w);

    // 2. fused projection GEMMs (all fp16 outputs)
    {
        dim3 gg(CC / BN, MM / BM, 3);  // (16, 64, 3)
        gemm_f16<<<gg, 256, GSMEM>>>(p_xk, p_xv, p_xr, p_w,
                                     nullptr, p_k16, p_v16, p_r16, 1);
    }

    // 3. fused WKV scan (one kernel) + sigmoid fusion
    {
        int blocks = BB * (CC / WCHAN);  // 512
        wkv_fused<<<blocks, WTHR>>>(p_k16, p_v16, p_r16, td, tf, p_s);
    }

    // 4. output GEMM into d_out (fp32 epilogue)
    {
        dim3 gg(CC / BN, MM / BM, 1);
        gemm_f16<<<gg, 256, GSMEM>>>(p_s, p_s, p_s, p_w + 3ULL * CC * CC,
                                     out, nullptr, nullptr, nullptr, 0);
    }
}